// round 5
// baseline (speedup 1.0000x reference)
#include <cuda_runtime.h>
#include <cuda_bf16.h>
#include <cstdint>
#include <cstddef>

#define B 2
#define T 2048
#define D 2048
#define H 16
#define HD 128
#define E 8
#define FH 8192
#define EPSV 1e-6f
#define MT (B*T)

// ---------------- scratch (device globals; no allocation) ----------------
__device__ float g_xn  [(size_t)B*T*D];
__device__ float g_q   [(size_t)B*T*D];
__device__ float g_k   [(size_t)B*T*D];
__device__ float g_v   [(size_t)B*T*D];
__device__ float g_attn[(size_t)B*T*D];
__device__ float g_h   [(size_t)B*T*D];
__device__ float g_hn  [(size_t)B*T*D];
__device__ float g_logits[(size_t)B*T*E];
__device__ float g_disp  [(size_t)B*T*E];
__device__ float g_comb  [(size_t)B*T*E];
__device__ float g_slots [(size_t)B*E*D];
__device__ float g_gact  [(size_t)B*E*FH];
#define KS 8
__device__ float g_ypart[(size_t)KS*B*E*D];
__device__ float g_y    [(size_t)B*E*D];
// bf16 split operands for tensor-core GEMMs
__device__ __nv_bfloat16 g_ah[(size_t)MT*D];
__device__ __nv_bfloat16 g_al[(size_t)MT*D];
__device__ __nv_bfloat16 g_wth[(size_t)4*D*D];   // W^T hi, 4 weights
__device__ __nv_bfloat16 g_wtl[(size_t)4*D*D];   // W^T lo

// ---------------- helpers ----------------
__device__ __forceinline__ uint32_t smem_u32(const void* p) {
    uint32_t a;
    asm("{ .reg .u64 t; cvta.to.shared.u64 t, %1; cvt.u32.u64 %0, t; }" : "=r"(a) : "l"(p));
    return a;
}
__device__ __forceinline__ void cp_async16(uint32_t saddr, const void* gaddr) {
    asm volatile("cp.async.ca.shared.global [%0], [%1], 16;" :: "r"(saddr), "l"(gaddr));
}
__device__ __forceinline__ void cp_commit() {
    asm volatile("cp.async.commit_group;");
}
template<int N>
__device__ __forceinline__ void cp_wait() {
    asm volatile("cp.async.wait_group %0;" :: "n"(N));
}
__device__ __forceinline__ void ldmx4(uint32_t* r, uint32_t addr) {
    asm volatile("ldmatrix.sync.aligned.m8n8.x4.shared.b16 {%0,%1,%2,%3}, [%4];"
                 : "=r"(r[0]), "=r"(r[1]), "=r"(r[2]), "=r"(r[3]) : "r"(addr));
}
__device__ __forceinline__ void mma16816(float* c, const uint32_t* a, uint32_t b0, uint32_t b1) {
    asm volatile(
        "mma.sync.aligned.m16n8k16.row.col.f32.bf16.bf16.f32 "
        "{%0,%1,%2,%3}, {%4,%5,%6,%7}, {%8,%9}, {%0,%1,%2,%3};"
        : "+f"(c[0]), "+f"(c[1]), "+f"(c[2]), "+f"(c[3])
        : "r"(a[0]), "r"(a[1]), "r"(a[2]), "r"(a[3]), "r"(b0), "r"(b1));
}

// ---------------- rmsnorm ----------------
__global__ void rmsnorm_kernel(const float* __restrict__ x, const float* __restrict__ w,
                               float* __restrict__ out) {
    int row = blockIdx.x;
    const float* xp = x + (size_t)row * D;
    float v[8];
    float ss = 0.f;
#pragma unroll
    for (int i = 0; i < 8; i++) { v[i] = xp[threadIdx.x + i*256]; ss += v[i]*v[i]; }
    __shared__ float red[256];
    red[threadIdx.x] = ss; __syncthreads();
    for (int s = 128; s > 0; s >>= 1) {
        if (threadIdx.x < s) red[threadIdx.x] += red[threadIdx.x + s];
        __syncthreads();
    }
    float rms = rsqrtf(red[0] / (float)D + EPSV);
    float* op = out + (size_t)row * D;
#pragma unroll
    for (int i = 0; i < 8; i++) { int d = threadIdx.x + i*256; op[d] = v[i]*rms*w[d]; }
}

// ---------------- split fp32 -> bf16 hi/lo ----------------
__global__ void asplit_kernel(const float* __restrict__ x,
                              __nv_bfloat16* __restrict__ hi, __nv_bfloat16* __restrict__ lo) {
    size_t idx = (size_t)blockIdx.x * 256 + threadIdx.x;   // over elems/4
    float4 v = ((const float4*)x)[idx];
    __nv_bfloat16 h0 = __float2bfloat16_rn(v.x), h1 = __float2bfloat16_rn(v.y);
    __nv_bfloat16 h2 = __float2bfloat16_rn(v.z), h3 = __float2bfloat16_rn(v.w);
    __nv_bfloat162* hp = (__nv_bfloat162*)hi;
    __nv_bfloat162* lp = (__nv_bfloat162*)lo;
    hp[2*idx+0] = __nv_bfloat162(h0, h1);
    hp[2*idx+1] = __nv_bfloat162(h2, h3);
    lp[2*idx+0] = __nv_bfloat162(__float2bfloat16_rn(v.x - __bfloat162float(h0)),
                                 __float2bfloat16_rn(v.y - __bfloat162float(h1)));
    lp[2*idx+1] = __nv_bfloat162(__float2bfloat16_rn(v.z - __bfloat162float(h2)),
                                 __float2bfloat16_rn(v.w - __bfloat162float(h3)));
}

// ---------------- transpose + split weights: W[K,N] -> WT[N,K] hi/lo bf16 ----------------
__global__ void wsplit_kernel(const float* __restrict__ W,
                              __nv_bfloat16* __restrict__ th, __nv_bfloat16* __restrict__ tl) {
    __shared__ float t[32][33];
    int n0 = blockIdx.x * 32, k0 = blockIdx.y * 32;
    int tx = threadIdx.x, ty = threadIdx.y;   // 32 x 8
#pragma unroll
    for (int i = 0; i < 4; i++)
        t[ty + 8*i][tx] = W[(size_t)(k0 + ty + 8*i) * D + n0 + tx];
    __syncthreads();
#pragma unroll
    for (int i = 0; i < 4; i++) {
        float v = t[tx][ty + 8*i];
        size_t o = (size_t)(n0 + ty + 8*i) * D + k0 + tx;
        __nv_bfloat16 hv = __float2bfloat16_rn(v);
        th[o] = hv;
        tl[o] = __float2bfloat16_rn(v - __bfloat162float(hv));
    }
}

// ---------------- mma.sync GEMM: C[M,N] = A[M,K] @ B^T (B given [N,K]) ----------------
// A = Ah + Al, B = Bh + Bl (bf16). D = AhBh + AhBl + AlBh, fp32 accum.
#define GM 128
#define GN 128
#define GK 32
#define TSTR 40                           // padded row stride in bf16 elems
#define TILE_B2 (128*TSTR*2)              // 10240 bytes per tile
#define STG_B2 (4*TILE_B2)                // 40960 bytes per stage
#define MMA_SMEM (2*STG_B2)               // 81920

__global__ __launch_bounds__(256, 2)
void mma_gemm_kernel(const __nv_bfloat16* __restrict__ Ah, const __nv_bfloat16* __restrict__ Al,
                     const __nv_bfloat16* __restrict__ Bh, const __nv_bfloat16* __restrict__ Bl,
                     const float* __restrict__ Res, float* __restrict__ C,
                     int Mdim, int Ndim, int Kdim) {
    extern __shared__ char smem[];
    uint32_t sb = smem_u32(smem);
    int tid = threadIdx.x, lane = tid & 31, warp = tid >> 5;
    int wm = warp & 3, wn = warp >> 2;        // warp tile: 32(m) x 64(n)
    int m0 = blockIdx.y * GM, n0 = blockIdx.x * GN;

    // gmem->smem geometry: 2 chunks of 16B per tile per thread
    int lrow[2], lcol[2];
    uint32_t sdst[2];
#pragma unroll
    for (int p = 0; p < 2; p++) {
        int idx = tid + p*256;               // 512 chunks
        lrow[p] = idx >> 2;
        lcol[p] = (idx & 3) * 8;
        sdst[p] = (uint32_t)(lrow[p]*TSTR + lcol[p]) * 2;
    }

    const int nkt = Kdim / GK;

    auto issue = [&](int kt, int stage) {
        uint32_t s0 = sb + stage * STG_B2;
        const __nv_bfloat16* srcs[4] = {
            Ah + (size_t)m0 * Kdim, Al + (size_t)m0 * Kdim,
            Bh + (size_t)n0 * Kdim, Bl + (size_t)n0 * Kdim };
#pragma unroll
        for (int tl = 0; tl < 4; tl++) {
#pragma unroll
            for (int p = 0; p < 2; p++) {
                const __nv_bfloat16* g = srcs[tl] + (size_t)lrow[p] * Kdim + kt*GK + lcol[p];
                cp_async16(s0 + tl*TILE_B2 + sdst[p], g);
            }
        }
        cp_commit();
    };

    float acc[2][8][4];
#pragma unroll
    for (int mi = 0; mi < 2; mi++)
#pragma unroll
        for (int nj = 0; nj < 8; nj++)
#pragma unroll
            for (int c = 0; c < 4; c++) acc[mi][nj][c] = 0.f;

    // ldmatrix addressing (same pattern for A and B tiles)
    int lr = lane & 15, lc8 = (lane >> 4) << 3;

    issue(0, 0);

    for (int kt = 0; kt < nkt; kt++) {
        int stage = kt & 1;
        if (kt + 1 < nkt) { issue(kt + 1, stage ^ 1); cp_wait<1>(); }
        else              { cp_wait<0>(); }
        __syncthreads();

        uint32_t s0 = sb + stage * STG_B2;
        uint32_t sAh = s0, sAl = s0 + TILE_B2, sBh = s0 + 2*TILE_B2, sBl = s0 + 3*TILE_B2;

#pragma unroll
        for (int ks = 0; ks < 2; ks++) {
            int kc = ks*16 + lc8;
            uint32_t ah[2][4], al[2][4], bh[4][4], bl[4][4];
#pragma unroll
            for (int mi = 0; mi < 2; mi++)
                ldmx4(ah[mi], sAh + (uint32_t)((wm*32 + mi*16 + lr)*TSTR + kc) * 2);
#pragma unroll
            for (int njp = 0; njp < 4; njp++)
                ldmx4(bh[njp], sBh + (uint32_t)((wn*64 + njp*16 + lr)*TSTR + kc) * 2);
            // Ah x Bh
#pragma unroll
            for (int mi = 0; mi < 2; mi++)
#pragma unroll
                for (int njp = 0; njp < 4; njp++) {
                    mma16816(acc[mi][2*njp+0], ah[mi], bh[njp][0], bh[njp][2]);
                    mma16816(acc[mi][2*njp+1], ah[mi], bh[njp][1], bh[njp][3]);
                }
            // Al x Bh
#pragma unroll
            for (int mi = 0; mi < 2; mi++)
                ldmx4(al[mi], sAl + (uint32_t)((wm*32 + mi*16 + lr)*TSTR + kc) * 2);
#pragma unroll
            for (int mi = 0; mi < 2; mi++)
#pragma unroll
                for (int njp = 0; njp < 4; njp++) {
                    mma16816(acc[mi][2*njp+0], al[mi], bh[njp][0], bh[njp][2]);
                    mma16816(acc[mi][2*njp+1], al[mi], bh[njp][1], bh[njp][3]);
                }
            // Ah x Bl
#pragma unroll
            for (int njp = 0; njp < 4; njp++)
                ldmx4(bl[njp], sBl + (uint32_t)((wn*64 + njp*16 + lr)*TSTR + kc) * 2);
#pragma unroll
            for (int mi = 0; mi < 2; mi++)
#pragma unroll
                for (int njp = 0; njp < 4; njp++) {
                    mma16816(acc[mi][2*njp+0], ah[mi], bl[njp][0], bl[njp][2]);
                    mma16816(acc[mi][2*njp+1], ah[mi], bl[njp][1], bl[njp][3]);
                }
        }
        __syncthreads();
    }

    // epilogue
    int g = lane >> 2, tg = lane & 3;
#pragma unroll
    for (int mi = 0; mi < 2; mi++) {
        size_t row0 = (size_t)(m0 + wm*32 + mi*16 + g);
#pragma unroll
        for (int nj = 0; nj < 8; nj++) {
            size_t col = (size_t)(n0 + wn*64 + nj*8 + tg*2);
            float2 v0 = make_float2(acc[mi][nj][0], acc[mi][nj][1]);
            float2 v1 = make_float2(acc[mi][nj][2], acc[mi][nj][3]);
            if (Res) {
                float2 r0 = *(const float2*)(Res + row0*Ndim + col);
                float2 r1 = *(const float2*)(Res + (row0+8)*Ndim + col);
                v0.x += r0.x; v0.y += r0.y; v1.x += r1.x; v1.y += r1.y;
            }
            *(float2*)(C + row0*Ndim + col) = v0;
            *(float2*)(C + (row0+8)*Ndim + col) = v1;
        }
    }
}

// ---------------- RoPE (in-place on q and k) ----------------
__global__ void rope_kernel(float* __restrict__ q, float* __restrict__ k,
                            const float* __restrict__ fc) {
    int idx = blockIdx.x * 256 + threadIdx.x;   // over B*T*H*64 pairs
    int i = idx & 63;
    int t = (idx >> 10) & (T - 1);              // H*64 = 1024
    float2 cs = *(const float2*)(fc + (size_t)t*HD + 2*i);
    float2 qv = ((const float2*)q)[idx];
    float2 kv = ((const float2*)k)[idx];
    ((float2*)q)[idx] = make_float2(qv.x*cs.x - qv.y*cs.y, qv.x*cs.y + qv.y*cs.x);
    ((float2*)k)[idx] = make_float2(kv.x*cs.x - kv.y*cs.y, kv.x*cs.y + kv.y*cs.x);
}

// ---------------- flash attention (fp32, online softmax) ----------------
#define BQ 64
#define BKV 64
#define KST (HD + 4)                     // padded smem row stride (132)
#define PSTR (BKV + 1)
#define ATTN_SMEM ((2*BKV*KST + BQ*PSTR) * (int)sizeof(float))

__global__ __launch_bounds__(256)
void attn_kernel(const float* __restrict__ Q, const float* __restrict__ Kg,
                 const float* __restrict__ Vg, float* __restrict__ Og,
                 const int* __restrict__ causal_flag) {
    extern __shared__ float sm[];
    float* ks = sm;                       // BKV x KST
    float* vs = sm + BKV*KST;             // BKV x KST
    float* ps = sm + 2*BKV*KST;           // BQ x PSTR

    int q0 = blockIdx.x * BQ;
    int h  = blockIdx.y;
    int b  = blockIdx.z;
    int tid = threadIdx.x;
    int tq = tid >> 2;                    // query within tile (0..63)
    int tg = tid & 3;                     // dim-group (0..3)
    bool causal = (*causal_flag) != 0;
    const float scale = 0.08838834764831845f;   // 1/sqrt(128)

    float qa[32], oa[32];
    {
        const float* qrow = Q + (((size_t)b*T + q0 + tq)*H + h)*HD;
#pragma unroll
        for (int i = 0; i < 8; i++) {
            float4 t4 = *(const float4*)(qrow + i*16 + tg*4);
            qa[i*4+0] = t4.x*scale; qa[i*4+1] = t4.y*scale;
            qa[i*4+2] = t4.z*scale; qa[i*4+3] = t4.w*scale;
            oa[i*4+0] = 0.f; oa[i*4+1] = 0.f; oa[i*4+2] = 0.f; oa[i*4+3] = 0.f;
        }
    }
    float m_run = -1e30f, l_run = 0.f;

    int kend = causal ? (q0 + BQ) : T;
    for (int k0 = 0; k0 < kend; k0 += BKV) {
        __syncthreads();
        {
            const float* kbase = Kg + (((size_t)b*T + k0)*H + h)*HD;
            const float* vbase = Vg + (((size_t)b*T + k0)*H + h)*HD;
#pragma unroll
            for (int p = 0; p < 8; p++) {
                int idx = tid + p*256;
                int r = idx >> 5, c4 = (idx & 31) * 4;
                *(float4*)(ks + r*KST + c4) = *(const float4*)(kbase + (size_t)r*D + c4);
                *(float4*)(vs + r*KST + c4) = *(const float4*)(vbase + (size_t)r*D + c4);
            }
        }
        __syncthreads();

        float m_tile = -1e30f;
#pragma unroll 4
        for (int j = 0; j < BKV; j++) {
            const float* kr = ks + j*KST;
            float acc = 0.f;
#pragma unroll
            for (int i = 0; i < 8; i++) {
                float4 kv = *(const float4*)(kr + i*16 + tg*4);
                acc += qa[i*4+0]*kv.x + qa[i*4+1]*kv.y + qa[i*4+2]*kv.z + qa[i*4+3]*kv.w;
            }
            acc += __shfl_xor_sync(0xffffffffu, acc, 1);
            acc += __shfl_xor_sync(0xffffffffu, acc, 2);
            if (causal && (k0 + j > q0 + tq)) acc = -1e30f;
            m_tile = fmaxf(m_tile, acc);
            if (tg == (j & 3)) ps[tq*PSTR + j] = acc;
        }
        float m_new = fmaxf(m_run, m_tile);
        float alpha = __expf(m_run - m_new);
        __syncwarp();
        float lsum = 0.f;
#pragma unroll
        for (int jj = 0; jj < 16; jj++) {
            int j = tg*16 + jj;
            float p = __expf(ps[tq*PSTR + j] - m_new);
            ps[tq*PSTR + j] = p;
            lsum += p;
        }
        lsum += __shfl_xor_sync(0xffffffffu, lsum, 1);
        lsum += __shfl_xor_sync(0xffffffffu, lsum, 2);
        l_run = l_run * alpha + lsum;
        m_run = m_new;
        __syncwarp();
#pragma unroll
        for (int i = 0; i < 32; i++) oa[i] *= alpha;
#pragma unroll 2
        for (int j = 0; j < BKV; j++) {
            float p = ps[tq*PSTR + j];
            const float* vr = vs + j*KST;
#pragma unroll
            for (int i = 0; i < 8; i++) {
                float4 vv = *(const float4*)(vr + i*16 + tg*4);
                oa[i*4+0] += p*vv.x; oa[i*4+1] += p*vv.y;
                oa[i*4+2] += p*vv.z; oa[i*4+3] += p*vv.w;
            }
        }
    }
    float invl = 1.f / l_run;
    float* orow = Og + (((size_t)b*T + q0 + tq)*H + h)*HD;
#pragma unroll
    for (int i = 0; i < 8; i++) {
        float4 w4;
        w4.x = oa[i*4+0]*invl; w4.y = oa[i*4+1]*invl;
        w4.z = oa[i*4+2]*invl; w4.w = oa[i*4+3]*invl;
        *(float4*)(orow + i*16 + tg*4) = w4;
    }
}

// ---------------- router logits: hn @ slots_w (D x E) ----------------
__global__ void logits_kernel(const float* __restrict__ hn, const float* __restrict__ sw,
                              float* __restrict__ out) {
    int row = blockIdx.x;
    const float* hp = hn + (size_t)row * D;
    float acc[E];
#pragma unroll
    for (int e = 0; e < E; e++) acc[e] = 0.f;
#pragma unroll
    for (int i = 0; i < 8; i++) {
        int d = threadIdx.x + i*256;
        float hv = hp[d];
        const float* swp = sw + (size_t)d * E;
#pragma unroll
        for (int e = 0; e < E; e++) acc[e] += hv * swp[e];
    }
#pragma unroll
    for (int e = 0; e < E; e++)
        for (int o = 16; o > 0; o >>= 1) acc[e] += __shfl_xor_sync(0xffffffffu, acc[e], o);
    __shared__ float red[8][E];
    int warp = threadIdx.x >> 5, lane = threadIdx.x & 31;
    if (lane == 0)
#pragma unroll
        for (int e = 0; e < E; e++) red[warp][e] = acc[e];
    __syncthreads();
    if (threadIdx.x < E) {
        float s = 0.f;
#pragma unroll
        for (int w = 0; w < 8; w++) s += red[w][threadIdx.x];
        out[(size_t)row*E + threadIdx.x] = s;
    }
}

// ---------------- dispatch softmax (over T, per (b,e)) ----------------
__global__ void dispatch_softmax_kernel(const float* __restrict__ lg, float* __restrict__ out) {
    int b = blockIdx.x >> 3, e = blockIdx.x & 7;
    const float* lp = lg + (size_t)b*T*E + e;
    float v[8];
    float m = -1e30f;
#pragma unroll
    for (int i = 0; i < 8; i++) {
        v[i] = lp[(size_t)(threadIdx.x + i*256)*E];
        m = fmaxf(m, v[i]);
    }
    __shared__ float red[256];
    red[threadIdx.x] = m; __syncthreads();
    for (int s = 128; s > 0; s >>= 1) {
        if (threadIdx.x < s) red[threadIdx.x] = fmaxf(red[threadIdx.x], red[threadIdx.x + s]);
        __syncthreads();
    }
    m = red[0]; __syncthreads();
    float ssum = 0.f;
#pragma unroll
    for (int i = 0; i < 8; i++) { v[i] = __expf(v[i] - m); ssum += v[i]; }
    red[threadIdx.x] = ssum; __syncthreads();
    for (int s = 128; s > 0; s >>= 1) {
        if (threadIdx.x < s) red[threadIdx.x] += red[threadIdx.x + s];
        __syncthreads();
    }
    float inv = 1.f / red[0];
    float* op = out + (size_t)b*T*E + e;
#pragma unroll
    for (int i = 0; i < 8; i++) op[(size_t)(threadIdx.x + i*256)*E] = v[i]*inv;
}

// ---------------- combine softmax (over E, per (b,t)) ----------------
__global__ void combine_softmax_kernel(const float* __restrict__ lg, float* __restrict__ out) {
    int row = blockIdx.x*256 + threadIdx.x;
    const float* lp = lg + (size_t)row * E;
    float m = -1e30f;
#pragma unroll
    for (int e = 0; e < E; e++) m = fmaxf(m, lp[e]);
    float ve[E]; float s = 0.f;
#pragma unroll
    for (int e = 0; e < E; e++) { ve[e] = __expf(lp[e] - m); s += ve[e]; }
    float inv = 1.f / s;
    float* op = out + (size_t)row * E;
#pragma unroll
    for (int e = 0; e < E; e++) op[e] = ve[e]*inv;
}

// ---------------- slots = dispatch^T @ hn (per b) ----------------
__global__ void slots_kernel(const float* __restrict__ disp, const float* __restrict__ hn,
                             float* __restrict__ slots) {
    int d = blockIdx.x*256 + threadIdx.x;
    int e = blockIdx.y, b = blockIdx.z;
    __shared__ float sd[256];
    float acc = 0.f;
    for (int t0 = 0; t0 < T; t0 += 256) {
        __syncthreads();
        sd[threadIdx.x] = disp[((size_t)b*T + t0 + threadIdx.x)*E + e];
        __syncthreads();
        const float* hp = hn + ((size_t)b*T + t0)*D + d;
#pragma unroll 8
        for (int tt = 0; tt < 256; tt++) acc += sd[tt] * hp[(size_t)tt*D];
    }
    slots[((size_t)b*E + e)*D + d] = acc;
}

// ---------------- expert up-proj: silu(slots@w1) * (slots@w3) ----------------
__global__ void gact_kernel(const float* __restrict__ slots, const float* __restrict__ w1,
                            const float* __restrict__ w3, float* __restrict__ gact) {
    int hcol = blockIdx.x*256 + threadIdx.x;
    int e = blockIdx.y;
    __shared__ float s0[D], s1[D];
    for (int i = threadIdx.x; i < D; i += 256) {
        s0[i] = slots[((size_t)0*E + e)*D + i];
        s1[i] = slots[((size_t)1*E + e)*D + i];
    }
    __syncthreads();
    float a10 = 0.f, a11 = 0.f, a30 = 0.f, a31 = 0.f;
    const float* w1p = w1 + (size_t)e*D*FH + hcol;
    const float* w3p = w3 + (size_t)e*D*FH + hcol;
#pragma unroll 4
    for (int dd = 0; dd < D; dd++) {
        float w1v = w1p[(size_t)dd*FH];
        float w3v = w3p[(size_t)dd*FH];
        a10 += s0[dd]*w1v; a11 += s1[dd]*w1v;
        a30 += s0[dd]*w3v; a31 += s1[dd]*w3v;
    }
    float g0 = a10 / (1.f + __expf(-a10)) * a30;
    float g1 = a11 / (1.f + __expf(-a11)) * a31;
    gact[((size_t)0*E + e)*FH + hcol] = g0;
    gact[((size_t)1*E + e)*FH + hcol] = g1;
}

// ---------------- expert down-proj, split-K partials ----------------
__global__ void w2_kernel(const float* __restrict__ gact, const float* __restrict__ w2,
                          float* __restrict__ ypart) {
    const int CH = FH / KS;                 // 1024
    int d = blockIdx.x*256 + threadIdx.x;
    int e = blockIdx.y;
    int kc = blockIdx.z;
    __shared__ float gg0[FH / KS], gg1[FH / KS];
    for (int i = threadIdx.x; i < CH; i += 256) {
        gg0[i] = gact[((size_t)0*E + e)*FH + kc*CH + i];
        gg1[i] = gact[((size_t)1*E + e)*FH + kc*CH + i];
    }
    __syncthreads();
    float a0 = 0.f, a1 = 0.f;
    const float* w2p = w2 + ((size_t)e*FH + (size_t)kc*CH)*D + d;
#pragma unroll 4
    for (int hh = 0; hh < CH; hh++) {
        float wv = w2p[(size_t)hh*D];
        a0 += gg0[hh]*wv; a1 += gg1[hh]*wv;
    }
    ypart[((size_t)kc*B*E + 0*E + e)*D + d] = a0;
    ypart[((size_t)kc*B*E + 1*E + e)*D + d] = a1;
}

__global__ void yreduce_kernel(const float* __restrict__ ypart, float* __restrict__ y) {
    int i = blockIdx.x*256 + threadIdx.x;
    float s = 0.f;
#pragma unroll
    for (int kc = 0; kc < KS; kc++) s += ypart[(size_t)kc*B*E*D + i];
    y[i] = s;
}

// ---------------- final: out = h + combine @ y ----------------
__global__ void final_kernel(const float* __restrict__ h, const float* __restrict__ comb,
                             const float* __restrict__ y, float* __restrict__ out) {
    int row = blockIdx.x;
    int b = row / T;
    float c[E];
    const float* cp = comb + (size_t)row*E;
#pragma unroll
    for (int e = 0; e < E; e++) c[e] = cp[e];
#pragma unroll
    for (int i = 0; i < 8; i++) {
        int d = threadIdx.x + i*256;
        float acc = h[(size_t)row*D + d];
#pragma unroll
        for (int e = 0; e < E; e++) acc += c[e] * y[((size_t)b*E + e)*D + d];
        out[(size_t)row*D + d] = acc;
    }
}

// ---------------- launch ----------------
extern "C" void kernel_launch(void* const* d_in, const int* in_sizes, int n_in,
                              void* d_out, int out_size) {
    const float* x   = (const float*)d_in[0];   // q (== k == v)
    const float* fc  = (const float*)d_in[3];
    const float* wq  = (const float*)d_in[4];
    const float* wk  = (const float*)d_in[5];
    const float* wv  = (const float*)d_in[6];
    const float* wo  = (const float*)d_in[7];
    const float* sw  = (const float*)d_in[8];
    const float* w1  = (const float*)d_in[9];
    const float* w3  = (const float*)d_in[10];
    const float* w2  = (const float*)d_in[11];
    const float* anw = (const float*)d_in[12];
    const float* fnw = (const float*)d_in[13];
    const int* causal = (const int*)d_in[14];
    float* out = (float*)d_out;

    float *xn, *q, *k, *v, *attn, *h, *hn, *logits, *disp, *comb, *slots, *gact, *ypart, *y;
    __nv_bfloat16 *ah, *al, *wth, *wtl;
    cudaGetSymbolAddress((void**)&xn,    g_xn);
    cudaGetSymbolAddress((void**)&q,     g_q);
    cudaGetSymbolAddress((void**)&k,     g_k);
    cudaGetSymbolAddress((void**)&v,     g_v);
    cudaGetSymbolAddress((void**)&attn,  g_attn);
    cudaGetSymbolAddress((void**)&h,     g_h);
    cudaGetSymbolAddress((void**)&hn,    g_hn);
    cudaGetSymbolAddress((void**)&logits,g_logits);
    cudaGetSymbolAddress((void**)&disp,  g_disp);
    cudaGetSymbolAddress((void**)&comb,  g_comb);
    cudaGetSymbolAddress((void**)&slots, g_slots);
    cudaGetSymbolAddress((void**)&gact,  g_gact);
    cudaGetSymbolAddress((void**)&ypart, g_ypart);
    cudaGetSymbolAddress((void**)&y,     g_y);
    cudaGetSymbolAddress((void**)&ah,    g_ah);
    cudaGetSymbolAddress((void**)&al,    g_al);
    cudaGetSymbolAddress((void**)&wth,   g_wth);
    cudaGetSymbolAddress((void**)&wtl,   g_wtl);

    cudaFuncSetAttribute(attn_kernel, cudaFuncAttributeMaxDynamicSharedMemorySize, ATTN_SMEM);
    cudaFuncSetAttribute(mma_gemm_kernel, cudaFuncAttributeMaxDynamicSharedMemorySize, MMA_SMEM);

    const size_t NK = (size_t)D * D;

    rmsnorm_kernel<<<MT, 256>>>(x, anw, xn);
    asplit_kernel<<<(MT*(size_t)D/4)/256, 256>>>(xn, ah, al);

    dim3 wgrid(D/32, D/32);
    wsplit_kernel<<<wgrid, dim3(32,8)>>>(wq, wth + 0*NK, wtl + 0*NK);
    wsplit_kernel<<<wgrid, dim3(32,8)>>>(wk, wth + 1*NK, wtl + 1*NK);
    wsplit_kernel<<<wgrid, dim3(32,8)>>>(wv, wth + 2*NK, wtl + 2*NK);
    wsplit_kernel<<<wgrid, dim3(32,8)>>>(wo, wth + 3*NK, wtl + 3*NK);

    dim3 gg(D/GN, MT/GM);
    mma_gemm_kernel<<<gg, 256, MMA_SMEM>>>(ah, al, wth + 0*NK, wtl + 0*NK, nullptr, q, MT, D, D);
    mma_gemm_kernel<<<gg, 256, MMA_SMEM>>>(ah, al, wth + 1*NK, wtl + 1*NK, nullptr, k, MT, D, D);
    mma_gemm_kernel<<<gg, 256, MMA_SMEM>>>(ah, al, wth + 2*NK, wtl + 2*NK, nullptr, v, MT, D, D);

    rope_kernel<<<(B*T*H*(HD/2))/256, 256>>>(q, k, fc);

    attn_kernel<<<dim3(T/BQ, H, B), 256, ATTN_SMEM>>>(q, k, v, attn, causal);

    asplit_kernel<<<(MT*(size_t)D/4)/256, 256>>>(attn, ah, al);
    mma_gemm_kernel<<<gg, 256, MMA_SMEM>>>(ah, al, wth + 3*NK, wtl + 3*NK, xn, h, MT, D, D);

    rmsnorm_kernel<<<MT, 256>>>(h, fnw, hn);

    logits_kernel<<<MT, 256>>>(hn, sw, logits);
    dispatch_softmax_kernel<<<B*E, 256>>>(logits, disp);
    combine_softmax_kernel<<<MT/256, 256>>>(logits, comb);

    slots_kernel<<<dim3(D/256, E, B), 256>>>(disp, hn, slots);
    gact_kernel<<<dim3(FH/256, E), 256>>>(slots, w1, w3, gact);
    w2_kernel<<<dim3(D/256, E, KS), 256>>>(gact, w2, ypart);
    yreduce_kernel<<<(B*E*D)/256, 256>>>(ypart, y);

    final_kernel<<<MT, 256>>>(h, comb, y, out);
}

// round 6
// speedup vs baseline: 1.0162x; 1.0162x over previous
#include <cuda_runtime.h>
#include <cuda_bf16.h>
#include <cstdint>
#include <cstddef>

#define B 2
#define T 2048
#define D 2048
#define H 16
#define HD 128
#define E 8
#define FH 8192
#define EPSV 1e-6f
#define MT (B*T)

// ---------------- scratch (device globals; no allocation) ----------------
__device__ float g_xn  [(size_t)B*T*D];
__device__ float g_q   [(size_t)B*T*D];
__device__ float g_k   [(size_t)B*T*D];
__device__ float g_v   [(size_t)B*T*D];
__device__ float g_attn[(size_t)B*T*D];
__device__ float g_h   [(size_t)B*T*D];
__device__ float g_hn  [(size_t)B*T*D];
__device__ float g_logits[(size_t)B*T*E];
__device__ float g_disp  [(size_t)B*T*E];
__device__ float g_comb  [(size_t)B*T*E];
__device__ float g_slots [(size_t)B*E*D];
__device__ float g_gact  [(size_t)B*E*FH];
#define KS 8
__device__ float g_ypart[(size_t)KS*B*E*D];
__device__ float g_y    [(size_t)B*E*D];
// bf16 split operands for tensor-core GEMMs
__device__ __nv_bfloat16 g_ah[(size_t)MT*D];
__device__ __nv_bfloat16 g_al[(size_t)MT*D];
__device__ __nv_bfloat16 g_wth[(size_t)4*D*D];   // W^T hi, 4 weights
__device__ __nv_bfloat16 g_wtl[(size_t)4*D*D];   // W^T lo

// ---------------- helpers ----------------
__device__ __forceinline__ uint32_t smem_u32(const void* p) {
    uint32_t a;
    asm("{ .reg .u64 t; cvta.to.shared.u64 t, %1; cvt.u32.u64 %0, t; }" : "=r"(a) : "l"(p));
    return a;
}
__device__ __forceinline__ void cp_async16(uint32_t saddr, const void* gaddr) {
    asm volatile("cp.async.ca.shared.global [%0], [%1], 16;" :: "r"(saddr), "l"(gaddr));
}
__device__ __forceinline__ void cp_commit() {
    asm volatile("cp.async.commit_group;");
}
template<int N>
__device__ __forceinline__ void cp_wait() {
    asm volatile("cp.async.wait_group %0;" :: "n"(N));
}
__device__ __forceinline__ void ldmx4(uint32_t* r, uint32_t addr) {
    asm volatile("ldmatrix.sync.aligned.m8n8.x4.shared.b16 {%0,%1,%2,%3}, [%4];"
                 : "=r"(r[0]), "=r"(r[1]), "=r"(r[2]), "=r"(r[3]) : "r"(addr));
}
__device__ __forceinline__ void mma16816(float* c, const uint32_t* a, uint32_t b0, uint32_t b1) {
    asm volatile(
        "mma.sync.aligned.m16n8k16.row.col.f32.bf16.bf16.f32 "
        "{%0,%1,%2,%3}, {%4,%5,%6,%7}, {%8,%9}, {%0,%1,%2,%3};"
        : "+f"(c[0]), "+f"(c[1]), "+f"(c[2]), "+f"(c[3])
        : "r"(a[0]), "r"(a[1]), "r"(a[2]), "r"(a[3]), "r"(b0), "r"(b1));
}

// ---------------- rmsnorm ----------------
__global__ void rmsnorm_kernel(const float* __restrict__ x, const float* __restrict__ w,
                               float* __restrict__ out) {
    int row = blockIdx.x;
    const float* xp = x + (size_t)row * D;
    float v[8];
    float ss = 0.f;
#pragma unroll
    for (int i = 0; i < 8; i++) { v[i] = xp[threadIdx.x + i*256]; ss += v[i]*v[i]; }
    __shared__ float red[256];
    red[threadIdx.x] = ss; __syncthreads();
    for (int s = 128; s > 0; s >>= 1) {
        if (threadIdx.x < s) red[threadIdx.x] += red[threadIdx.x + s];
        __syncthreads();
    }
    float rms = rsqrtf(red[0] / (float)D + EPSV);
    float* op = out + (size_t)row * D;
#pragma unroll
    for (int i = 0; i < 8; i++) { int d = threadIdx.x + i*256; op[d] = v[i]*rms*w[d]; }
}

// ---------------- split fp32 -> bf16 hi/lo ----------------
__global__ void asplit_kernel(const float* __restrict__ x,
                              __nv_bfloat16* __restrict__ hi, __nv_bfloat16* __restrict__ lo) {
    size_t idx = (size_t)blockIdx.x * 256 + threadIdx.x;   // over elems/4
    float4 v = ((const float4*)x)[idx];
    __nv_bfloat16 h0 = __float2bfloat16_rn(v.x), h1 = __float2bfloat16_rn(v.y);
    __nv_bfloat16 h2 = __float2bfloat16_rn(v.z), h3 = __float2bfloat16_rn(v.w);
    __nv_bfloat162* hp = (__nv_bfloat162*)hi;
    __nv_bfloat162* lp = (__nv_bfloat162*)lo;
    hp[2*idx+0] = __nv_bfloat162(h0, h1);
    hp[2*idx+1] = __nv_bfloat162(h2, h3);
    lp[2*idx+0] = __nv_bfloat162(__float2bfloat16_rn(v.x - __bfloat162float(h0)),
                                 __float2bfloat16_rn(v.y - __bfloat162float(h1)));
    lp[2*idx+1] = __nv_bfloat162(__float2bfloat16_rn(v.z - __bfloat162float(h2)),
                                 __float2bfloat16_rn(v.w - __bfloat162float(h3)));
}

// ---------------- transpose + split weights: W[K,N] -> WT[N,K] hi/lo bf16 ----------------
__global__ void wsplit_kernel(const float* __restrict__ W,
                              __nv_bfloat16* __restrict__ th, __nv_bfloat16* __restrict__ tl) {
    __shared__ float t[32][33];
    int n0 = blockIdx.x * 32, k0 = blockIdx.y * 32;
    int tx = threadIdx.x, ty = threadIdx.y;   // 32 x 8
#pragma unroll
    for (int i = 0; i < 4; i++)
        t[ty + 8*i][tx] = W[(size_t)(k0 + ty + 8*i) * D + n0 + tx];
    __syncthreads();
#pragma unroll
    for (int i = 0; i < 4; i++) {
        float v = t[tx][ty + 8*i];
        size_t o = (size_t)(n0 + ty + 8*i) * D + k0 + tx;
        __nv_bfloat16 hv = __float2bfloat16_rn(v);
        th[o] = hv;
        tl[o] = __float2bfloat16_rn(v - __bfloat162float(hv));
    }
}

// ---------------- mma.sync GEMM: C[M,N] = A[M,K] @ B^T (B given [N,K]) ----------------
// A = Ah + Al, B = Bh + Bl (bf16). D = AhBh + AhBl + AlBh, fp32 accum.
#define GM 128
#define GN 128
#define GK 32
#define TSTR 40                           // padded row stride in bf16 elems
#define TILE_B2 (128*TSTR*2)              // 10240 bytes per tile
#define STG_B2 (4*TILE_B2)                // 40960 bytes per stage
#define MMA_SMEM (2*STG_B2)               // 81920

__global__ __launch_bounds__(256, 2)
void mma_gemm_kernel(const __nv_bfloat16* __restrict__ Ah, const __nv_bfloat16* __restrict__ Al,
                     const __nv_bfloat16* __restrict__ Bh, const __nv_bfloat16* __restrict__ Bl,
                     const float* __restrict__ Res, float* __restrict__ C,
                     int Mdim, int Ndim, int Kdim) {
    extern __shared__ char smem[];
    uint32_t sb = smem_u32(smem);
    int tid = threadIdx.x, lane = tid & 31, warp = tid >> 5;
    int wm = warp & 3, wn = warp >> 2;        // warp tile: 32(m) x 64(n)
    int m0 = blockIdx.y * GM, n0 = blockIdx.x * GN;

    // gmem->smem geometry: 2 chunks of 16B per tile per thread
    int lrow[2], lcol[2];
    uint32_t sdst[2];
#pragma unroll
    for (int p = 0; p < 2; p++) {
        int idx = tid + p*256;               // 512 chunks
        lrow[p] = idx >> 2;
        lcol[p] = (idx & 3) * 8;
        sdst[p] = (uint32_t)(lrow[p]*TSTR + lcol[p]) * 2;
    }

    const int nkt = Kdim / GK;

    auto issue = [&](int kt, int stage) {
        uint32_t s0 = sb + stage * STG_B2;
        const __nv_bfloat16* srcs[4] = {
            Ah + (size_t)m0 * Kdim, Al + (size_t)m0 * Kdim,
            Bh + (size_t)n0 * Kdim, Bl + (size_t)n0 * Kdim };
#pragma unroll
        for (int tl = 0; tl < 4; tl++) {
#pragma unroll
            for (int p = 0; p < 2; p++) {
                const __nv_bfloat16* g = srcs[tl] + (size_t)lrow[p] * Kdim + kt*GK + lcol[p];
                cp_async16(s0 + tl*TILE_B2 + sdst[p], g);
            }
        }
        cp_commit();
    };

    float acc[2][8][4];
#pragma unroll
    for (int mi = 0; mi < 2; mi++)
#pragma unroll
        for (int nj = 0; nj < 8; nj++)
#pragma unroll
            for (int c = 0; c < 4; c++) acc[mi][nj][c] = 0.f;

    // ldmatrix addressing (same pattern for A and B tiles)
    int lr = lane & 15, lc8 = (lane >> 4) << 3;

    issue(0, 0);

    for (int kt = 0; kt < nkt; kt++) {
        int stage = kt & 1;
        if (kt + 1 < nkt) { issue(kt + 1, stage ^ 1); cp_wait<1>(); }
        else              { cp_wait<0>(); }
        __syncthreads();

        uint32_t s0 = sb + stage * STG_B2;
        uint32_t sAh = s0, sAl = s0 + TILE_B2, sBh = s0 + 2*TILE_B2, sBl = s0 + 3*TILE_B2;

#pragma unroll
        for (int ks = 0; ks < 2; ks++) {
            int kc = ks*16 + lc8;
            uint32_t ah[2][4], al[2][4], bh[4][4], bl[4][4];
#pragma unroll
            for (int mi = 0; mi < 2; mi++)
                ldmx4(ah[mi], sAh + (uint32_t)((wm*32 + mi*16 + lr)*TSTR + kc) * 2);
#pragma unroll
            for (int njp = 0; njp < 4; njp++)
                ldmx4(bh[njp], sBh + (uint32_t)((wn*64 + njp*16 + lr)*TSTR + kc) * 2);
            // Ah x Bh
#pragma unroll
            for (int mi = 0; mi < 2; mi++)
#pragma unroll
                for (int njp = 0; njp < 4; njp++) {
                    mma16816(acc[mi][2*njp+0], ah[mi], bh[njp][0], bh[njp][2]);
                    mma16816(acc[mi][2*njp+1], ah[mi], bh[njp][1], bh[njp][3]);
                }
            // Al x Bh
#pragma unroll
            for (int mi = 0; mi < 2; mi++)
                ldmx4(al[mi], sAl + (uint32_t)((wm*32 + mi*16 + lr)*TSTR + kc) * 2);
#pragma unroll
            for (int mi = 0; mi < 2; mi++)
#pragma unroll
                for (int njp = 0; njp < 4; njp++) {
                    mma16816(acc[mi][2*njp+0], al[mi], bh[njp][0], bh[njp][2]);
                    mma16816(acc[mi][2*njp+1], al[mi], bh[njp][1], bh[njp][3]);
                }
            // Ah x Bl
#pragma unroll
            for (int njp = 0; njp < 4; njp++)
                ldmx4(bl[njp], sBl + (uint32_t)((wn*64 + njp*16 + lr)*TSTR + kc) * 2);
#pragma unroll
            for (int mi = 0; mi < 2; mi++)
#pragma unroll
                for (int njp = 0; njp < 4; njp++) {
                    mma16816(acc[mi][2*njp+0], ah[mi], bl[njp][0], bl[njp][2]);
                    mma16816(acc[mi][2*njp+1], ah[mi], bl[njp][1], bl[njp][3]);
                }
        }
        __syncthreads();
    }

    // epilogue
    int g = lane >> 2, tg = lane & 3;
#pragma unroll
    for (int mi = 0; mi < 2; mi++) {
        size_t row0 = (size_t)(m0 + wm*32 + mi*16 + g);
#pragma unroll
        for (int nj = 0; nj < 8; nj++) {
            size_t col = (size_t)(n0 + wn*64 + nj*8 + tg*2);
            float2 v0 = make_float2(acc[mi][nj][0], acc[mi][nj][1]);
            float2 v1 = make_float2(acc[mi][nj][2], acc[mi][nj][3]);
            if (Res) {
                float2 r0 = *(const float2*)(Res + row0*Ndim + col);
                float2 r1 = *(const float2*)(Res + (row0+8)*Ndim + col);
                v0.x += r0.x; v0.y += r0.y; v1.x += r1.x; v1.y += r1.y;
            }
            *(float2*)(C + row0*Ndim + col) = v0;
            *(float2*)(C + (row0+8)*Ndim + col) = v1;
        }
    }
}

// ---------------- RoPE (in-place on q and k) ----------------
__global__ void rope_kernel(float* __restrict__ q, float* __restrict__ k,
                            const float* __restrict__ fc) {
    int idx = blockIdx.x * 256 + threadIdx.x;   // over B*T*H*64 pairs
    int i = idx & 63;
    int t = (idx >> 10) & (T - 1);              // H*64 = 1024
    float2 cs = *(const float2*)(fc + (size_t)t*HD + 2*i);
    float2 qv = ((const float2*)q)[idx];
    float2 kv = ((const float2*)k)[idx];
    ((float2*)q)[idx] = make_float2(qv.x*cs.x - qv.y*cs.y, qv.x*cs.y + qv.y*cs.x);
    ((float2*)k)[idx] = make_float2(kv.x*cs.x - kv.y*cs.y, kv.x*cs.y + kv.y*cs.x);
}

// ---------------- flash attention (fp32, online softmax) ----------------
#define BQ 64
#define BKV 64
#define KST (HD + 4)                     // padded smem row stride (132)
#define PSTR (BKV + 1)
#define ATTN_SMEM ((2*BKV*KST + BQ*PSTR) * (int)sizeof(float))

__global__ __launch_bounds__(256)
void attn_kernel(const float* __restrict__ Q, const float* __restrict__ Kg,
                 const float* __restrict__ Vg, float* __restrict__ Og,
                 const int* __restrict__ causal_flag) {
    extern __shared__ float sm[];
    float* ks = sm;                       // BKV x KST
    float* vs = sm + BKV*KST;             // BKV x KST
    float* ps = sm + 2*BKV*KST;           // BQ x PSTR

    int q0 = blockIdx.x * BQ;
    int h  = blockIdx.y;
    int b  = blockIdx.z;
    int tid = threadIdx.x;
    int tq = tid >> 2;                    // query within tile (0..63)
    int tg = tid & 3;                     // dim-group (0..3)
    bool causal = (*causal_flag) != 0;
    const float scale = 0.08838834764831845f;   // 1/sqrt(128)

    float qa[32], oa[32];
    {
        const float* qrow = Q + (((size_t)b*T + q0 + tq)*H + h)*HD;
#pragma unroll
        for (int i = 0; i < 8; i++) {
            float4 t4 = *(const float4*)(qrow + i*16 + tg*4);
            qa[i*4+0] = t4.x*scale; qa[i*4+1] = t4.y*scale;
            qa[i*4+2] = t4.z*scale; qa[i*4+3] = t4.w*scale;
            oa[i*4+0] = 0.f; oa[i*4+1] = 0.f; oa[i*4+2] = 0.f; oa[i*4+3] = 0.f;
        }
    }
    float m_run = -1e30f, l_run = 0.f;

    int kend = causal ? (q0 + BQ) : T;
    for (int k0 = 0; k0 < kend; k0 += BKV) {
        __syncthreads();
        {
            const float* kbase = Kg + (((size_t)b*T + k0)*H + h)*HD;
            const float* vbase = Vg + (((size_t)b*T + k0)*H + h)*HD;
#pragma unroll
            for (int p = 0; p < 8; p++) {
                int idx = tid + p*256;
                int r = idx >> 5, c4 = (idx & 31) * 4;
                *(float4*)(ks + r*KST + c4) = *(const float4*)(kbase + (size_t)r*D + c4);
                *(float4*)(vs + r*KST + c4) = *(const float4*)(vbase + (size_t)r*D + c4);
            }
        }
        __syncthreads();

        float m_tile = -1e30f;
#pragma unroll 4
        for (int j = 0; j < BKV; j++) {
            const float* kr = ks + j*KST;
            float acc = 0.f;
#pragma unroll
            for (int i = 0; i < 8; i++) {
                float4 kv = *(const float4*)(kr + i*16 + tg*4);
                acc += qa[i*4+0]*kv.x + qa[i*4+1]*kv.y + qa[i*4+2]*kv.z + qa[i*4+3]*kv.w;
            }
            acc += __shfl_xor_sync(0xffffffffu, acc, 1);
            acc += __shfl_xor_sync(0xffffffffu, acc, 2);
            if (causal && (k0 + j > q0 + tq)) acc = -1e30f;
            m_tile = fmaxf(m_tile, acc);
            if (tg == (j & 3)) ps[tq*PSTR + j] = acc;
        }
        float m_new = fmaxf(m_run, m_tile);
        float alpha = __expf(m_run - m_new);
        __syncwarp();
        float lsum = 0.f;
#pragma unroll
        for (int jj = 0; jj < 16; jj++) {
            int j = tg*16 + jj;
            float p = __expf(ps[tq*PSTR + j] - m_new);
            ps[tq*PSTR + j] = p;
            lsum += p;
        }
        lsum += __shfl_xor_sync(0xffffffffu, lsum, 1);
        lsum += __shfl_xor_sync(0xffffffffu, lsum, 2);
        l_run = l_run * alpha + lsum;
        m_run = m_new;
        __syncwarp();
#pragma unroll
        for (int i = 0; i < 32; i++) oa[i] *= alpha;
#pragma unroll 2
        for (int j = 0; j < BKV; j++) {
            float p = ps[tq*PSTR + j];
            const float* vr = vs + j*KST;
#pragma unroll
            for (int i = 0; i < 8; i++) {
                float4 vv = *(const float4*)(vr + i*16 + tg*4);
                oa[i*4+0] += p*vv.x; oa[i*4+1] += p*vv.y;
                oa[i*4+2] += p*vv.z; oa[i*4+3] += p*vv.w;
            }
        }
    }
    float invl = 1.f / l_run;
    float* orow = Og + (((size_t)b*T + q0 + tq)*H + h)*HD;
#pragma unroll
    for (int i = 0; i < 8; i++) {
        float4 w4;
        w4.x = oa[i*4+0]*invl; w4.y = oa[i*4+1]*invl;
        w4.z = oa[i*4+2]*invl; w4.w = oa[i*4+3]*invl;
        *(float4*)(orow + i*16 + tg*4) = w4;
    }
}

// ---------------- router logits: hn @ slots_w (D x E) ----------------
__global__ void logits_kernel(const float* __restrict__ hn, const float* __restrict__ sw,
                              float* __restrict__ out) {
    int row = blockIdx.x;
    const float* hp = hn + (size_t)row * D;
    float acc[E];
#pragma unroll
    for (int e = 0; e < E; e++) acc[e] = 0.f;
#pragma unroll
    for (int i = 0; i < 8; i++) {
        int d = threadIdx.x + i*256;
        float hv = hp[d];
        const float* swp = sw + (size_t)d * E;
#pragma unroll
        for (int e = 0; e < E; e++) acc[e] += hv * swp[e];
    }
#pragma unroll
    for (int e = 0; e < E; e++)
        for (int o = 16; o > 0; o >>= 1) acc[e] += __shfl_xor_sync(0xffffffffu, acc[e], o);
    __shared__ float red[8][E];
    int warp = threadIdx.x >> 5, lane = threadIdx.x & 31;
    if (lane == 0)
#pragma unroll
        for (int e = 0; e < E; e++) red[warp][e] = acc[e];
    __syncthreads();
    if (threadIdx.x < E) {
        float s = 0.f;
#pragma unroll
        for (int w = 0; w < 8; w++) s += red[w][threadIdx.x];
        out[(size_t)row*E + threadIdx.x] = s;
    }
}

// ---------------- dispatch softmax (over T, per (b,e)) ----------------
__global__ void dispatch_softmax_kernel(const float* __restrict__ lg, float* __restrict__ out) {
    int b = blockIdx.x >> 3, e = blockIdx.x & 7;
    const float* lp = lg + (size_t)b*T*E + e;
    float v[8];
    float m = -1e30f;
#pragma unroll
    for (int i = 0; i < 8; i++) {
        v[i] = lp[(size_t)(threadIdx.x + i*256)*E];
        m = fmaxf(m, v[i]);
    }
    __shared__ float red[256];
    red[threadIdx.x] = m; __syncthreads();
    for (int s = 128; s > 0; s >>= 1) {
        if (threadIdx.x < s) red[threadIdx.x] = fmaxf(red[threadIdx.x], red[threadIdx.x + s]);
        __syncthreads();
    }
    m = red[0]; __syncthreads();
    float ssum = 0.f;
#pragma unroll
    for (int i = 0; i < 8; i++) { v[i] = __expf(v[i] - m); ssum += v[i]; }
    red[threadIdx.x] = ssum; __syncthreads();
    for (int s = 128; s > 0; s >>= 1) {
        if (threadIdx.x < s) red[threadIdx.x] += red[threadIdx.x + s];
        __syncthreads();
    }
    float inv = 1.f / red[0];
    float* op = out + (size_t)b*T*E + e;
#pragma unroll
    for (int i = 0; i < 8; i++) op[(size_t)(threadIdx.x + i*256)*E] = v[i]*inv;
}

// ---------------- combine softmax (over E, per (b,t)) ----------------
__global__ void combine_softmax_kernel(const float* __restrict__ lg, float* __restrict__ out) {
    int row = blockIdx.x*256 + threadIdx.x;
    const float* lp = lg + (size_t)row * E;
    float m = -1e30f;
#pragma unroll
    for (int e = 0; e < E; e++) m = fmaxf(m, lp[e]);
    float ve[E]; float s = 0.f;
#pragma unroll
    for (int e = 0; e < E; e++) { ve[e] = __expf(lp[e] - m); s += ve[e]; }
    float inv = 1.f / s;
    float* op = out + (size_t)row * E;
#pragma unroll
    for (int e = 0; e < E; e++) op[e] = ve[e]*inv;
}

// ---------------- slots = dispatch^T @ hn (per b) ----------------
__global__ void slots_kernel(const float* __restrict__ disp, const float* __restrict__ hn,
                             float* __restrict__ slots) {
    int d = blockIdx.x*256 + threadIdx.x;
    int e = blockIdx.y, b = blockIdx.z;
    __shared__ float sd[256];
    float acc = 0.f;
    for (int t0 = 0; t0 < T; t0 += 256) {
        __syncthreads();
        sd[threadIdx.x] = disp[((size_t)b*T + t0 + threadIdx.x)*E + e];
        __syncthreads();
        const float* hp = hn + ((size_t)b*T + t0)*D + d;
#pragma unroll 8
        for (int tt = 0; tt < 256; tt++) acc += sd[tt] * hp[(size_t)tt*D];
    }
    slots[((size_t)b*E + e)*D + d] = acc;
}

// ---------------- expert up-proj: silu(slots@w1) * (slots@w3) ----------------
__global__ void gact_kernel(const float* __restrict__ slots, const float* __restrict__ w1,
                            const float* __restrict__ w3, float* __restrict__ gact) {
    int hcol = blockIdx.x*256 + threadIdx.x;
    int e = blockIdx.y;
    __shared__ float s0[D], s1[D];
    for (int i = threadIdx.x; i < D; i += 256) {
        s0[i] = slots[((size_t)0*E + e)*D + i];
        s1[i] = slots[((size_t)1*E + e)*D + i];
    }
    __syncthreads();
    float a10 = 0.f, a11 = 0.f, a30 = 0.f, a31 = 0.f;
    const float* w1p = w1 + (size_t)e*D*FH + hcol;
    const float* w3p = w3 + (size_t)e*D*FH + hcol;
#pragma unroll 4
    for (int dd = 0; dd < D; dd++) {
        float w1v = w1p[(size_t)dd*FH];
        float w3v = w3p[(size_t)dd*FH];
        a10 += s0[dd]*w1v; a11 += s1[dd]*w1v;
        a30 += s0[dd]*w3v; a31 += s1[dd]*w3v;
    }
    float g0 = a10 / (1.f + __expf(-a10)) * a30;
    float g1 = a11 / (1.f + __expf(-a11)) * a31;
    gact[((size_t)0*E + e)*FH + hcol] = g0;
    gact[((size_t)1*E + e)*FH + hcol] = g1;
}

// ---------------- expert down-proj, split-K partials ----------------
__global__ void w2_kernel(const float* __restrict__ gact, const float* __restrict__ w2,
                          float* __restrict__ ypart) {
    const int CH = FH / KS;                 // 1024
    int d = blockIdx.x*256 + threadIdx.x;
    int e = blockIdx.y;
    int kc = blockIdx.z;
    __shared__ float gg0[FH / KS], gg1[FH / KS];
    for (int i = threadIdx.x; i < CH; i += 256) {
        gg0[i] = gact[((size_t)0*E + e)*FH + kc*CH + i];
        gg1[i] = gact[((size_t)1*E + e)*FH + kc*CH + i];
    }
    __syncthreads();
    float a0 = 0.f, a1 = 0.f;
    const float* w2p = w2 + ((size_t)e*FH + (size_t)kc*CH)*D + d;
#pragma unroll 4
    for (int hh = 0; hh < CH; hh++) {
        float wv = w2p[(size_t)hh*D];
        a0 += gg0[hh]*wv; a1 += gg1[hh]*wv;
    }
    ypart[((size_t)kc*B*E + 0*E + e)*D + d] = a0;
    ypart[((size_t)kc*B*E + 1*E + e)*D + d] = a1;
}

__global__ void yreduce_kernel(const float* __restrict__ ypart, float* __restrict__ y) {
    int i = blockIdx.x*256 + threadIdx.x;
    float s = 0.f;
#pragma unroll
    for (int kc = 0; kc < KS; kc++) s += ypart[(size_t)kc*B*E*D + i];
    y[i] = s;
}

// ---------------- final: out = h + combine @ y ----------------
__global__ void final_kernel(const float* __restrict__ h, const float* __restrict__ comb,
                             const float* __restrict__ y, float* __restrict__ out) {
    int row = blockIdx.x;
    int b = row / T;
    float c[E];
    const float* cp = comb + (size_t)row*E;
#pragma unroll
    for (int e = 0; e < E; e++) c[e] = cp[e];
#pragma unroll
    for (int i = 0; i < 8; i++) {
        int d = threadIdx.x + i*256;
        float acc = h[(size_t)row*D + d];
#pragma unroll
        for (int e = 0; e < E; e++) acc += c[e] * y[((size_t)b*E + e)*D + d];
        out[(size_t)row*D + d] = acc;
    }
}

// ---------------- launch ----------------
extern "C" void kernel_launch(void* const* d_in, const int* in_sizes, int n_in,
                              void* d_out, int out_size) {
    const float* x   = (const float*)d_in[0];   // q (== k == v)
    const float* fc  = (const float*)d_in[3];
    const float* wq  = (const float*)d_in[4];
    const float* wk  = (const float*)d_in[5];
    const float* wv  = (const float*)d_in[6];
    const float* wo  = (const float*)d_in[7];
    const float* sw  = (const float*)d_in[8];
    const float* w1  = (const float*)d_in[9];
    const float* w3  = (const float*)d_in[10];
    const float* w2  = (const float*)d_in[11];
    const float* anw = (const float*)d_in[12];
    const float* fnw = (const float*)d_in[13];
    const int* causal = (const int*)d_in[14];
    float* out = (float*)d_out;

    float *xn, *q, *k, *v, *attn, *h, *hn, *logits, *disp, *comb, *slots, *gact, *ypart, *y;
    __nv_bfloat16 *ah, *al, *wth, *wtl;
    cudaGetSymbolAddress((void**)&xn,    g_xn);
    cudaGetSymbolAddress((void**)&q,     g_q);
    cudaGetSymbolAddress((void**)&k,     g_k);
    cudaGetSymbolAddress((void**)&v,     g_v);
    cudaGetSymbolAddress((void**)&attn,  g_attn);
    cudaGetSymbolAddress((void**)&h,     g_h);
    cudaGetSymbolAddress((void**)&hn,    g_hn);
    cudaGetSymbolAddress((void**)&logits,g_logits);
    cudaGetSymbolAddress((void**)&disp,  g_disp);
    cudaGetSymbolAddress((void**)&comb,  g_comb);
    cudaGetSymbolAddress((void**)&slots, g_slots);
    cudaGetSymbolAddress((void**)&gact,  g_gact);
    cudaGetSymbolAddress((void**)&ypart, g_ypart);
    cudaGetSymbolAddress((void**)&y,     g_y);
    cudaGetSymbolAddress((void**)&ah,    g_ah);
    cudaGetSymbolAddress((void**)&al,    g_al);
    cudaGetSymbolAddress((void**)&wth,   g_wth);
    cudaGetSymbolAddress((void**)&wtl,   g_wtl);

    cudaFuncSetAttribute(attn_kernel, cudaFuncAttributeMaxDynamicSharedMemorySize, ATTN_SMEM);
    cudaFuncSetAttribute(mma_gemm_kernel, cudaFuncAttributeMaxDynamicSharedMemorySize, MMA_SMEM);

    const size_t NK = (size_t)D * D;

    rmsnorm_kernel<<<MT, 256>>>(x, anw, xn);
    asplit_kernel<<<(MT*(size_t)D/4)/256, 256>>>(xn, ah, al);

    dim3 wgrid(D/32, D/32);
    wsplit_kernel<<<wgrid, dim3(32,8)>>>(wq, wth + 0*NK, wtl + 0*NK);
    wsplit_kernel<<<wgrid, dim3(32,8)>>>(wk, wth + 1*NK, wtl + 1*NK);
    wsplit_kernel<<<wgrid, dim3(32,8)>>>(wv, wth + 2*NK, wtl + 2*NK);
    wsplit_kernel<<<wgrid, dim3(32,8)>>>(wo, wth + 3*NK, wtl + 3*NK);

    dim3 gg(D/GN, MT/GM);
    mma_gemm_kernel<<<gg, 256, MMA_SMEM>>>(ah, al, wth + 0*NK, wtl + 0*NK, nullptr, q, MT, D, D);
    mma_gemm_kernel<<<gg, 256, MMA_SMEM>>>(ah, al, wth + 1*NK, wtl + 1*NK, nullptr, k, MT, D, D);
    mma_gemm_kernel<<<gg, 256, MMA_SMEM>>>(ah, al, wth + 2*NK, wtl + 2*NK, nullptr, v, MT, D, D);

    rope_kernel<<<(B*T*H*(HD/2))/256, 256>>>(q, k, fc);

    attn_kernel<<<dim3(T/BQ, H, B), 256, ATTN_SMEM>>>(q, k, v, attn, causal);

    asplit_kernel<<<(MT*(size_t)D/4)/256, 256>>>(attn, ah, al);
    mma_gemm_kernel<<<gg, 256, MMA_SMEM>>>(ah, al, wth + 3*NK, wtl + 3*NK, xn, h, MT, D, D);

    rmsnorm_kernel<<<MT, 256>>>(h, fnw, hn);

    logits_kernel<<<MT, 256>>>(hn, sw, logits);
    dispatch_softmax_kernel<<<B*E, 256>>>(logits, disp);
    combine_softmax_kernel<<<MT/256, 256>>>(logits, comb);

    slots_kernel<<<dim3(D/256, E, B), 256>>>(disp, hn, slots);
    gact_kernel<<<dim3(FH/256, E), 256>>>(slots, w1, w3, gact);
    w2_kernel<<<dim3(D/256, E, KS), 256>>>(gact, w2, ypart);
    yreduce_kernel<<<(B*E*D)/256, 256>>>(ypart, y);

    final_kernel<<<MT, 256>>>(h, comb, y, out);
}

// round 7
// speedup vs baseline: 1.9014x; 1.8711x over previous
#include <cuda_runtime.h>
#include <cuda_bf16.h>
#include <cstdint>
#include <cstddef>

#define B 2
#define T 2048
#define D 2048
#define H 16
#define HD 128
#define E 8
#define FH 8192
#define EPSV 1e-6f
#define MT (B*T)

// ---------------- scratch (device globals; no allocation) ----------------
__device__ float g_xn  [(size_t)B*T*D];
__device__ float g_q   [(size_t)B*T*D];
__device__ float g_k   [(size_t)B*T*D];
__device__ float g_v   [(size_t)B*T*D];
__device__ float g_attn[(size_t)B*T*D];
__device__ float g_h   [(size_t)B*T*D];
__device__ float g_hn  [(size_t)B*T*D];
__device__ float g_logits[(size_t)B*T*E];
__device__ float g_disp  [(size_t)B*T*E];
__device__ float g_comb  [(size_t)B*T*E];
__device__ float g_slots [(size_t)B*E*D];
__device__ float g_gact  [(size_t)B*E*FH];
#define KS 8
__device__ float g_ypart[(size_t)KS*B*E*D];
__device__ float g_y    [(size_t)B*E*D];
// bf16 split operands for tensor-core GEMMs / attention
__device__ __nv_bfloat16 g_ah[(size_t)MT*D];     // also reused as q-hi
__device__ __nv_bfloat16 g_al[(size_t)MT*D];     // also reused as q-lo
__device__ __nv_bfloat16 g_kh[(size_t)MT*D];
__device__ __nv_bfloat16 g_kl[(size_t)MT*D];
__device__ __nv_bfloat16 g_vh[(size_t)MT*D];
__device__ __nv_bfloat16 g_vl[(size_t)MT*D];
__device__ __nv_bfloat16 g_wth[(size_t)4*D*D];   // W^T hi, 4 weights
__device__ __nv_bfloat16 g_wtl[(size_t)4*D*D];   // W^T lo

// ---------------- helpers ----------------
__device__ __forceinline__ uint32_t smem_u32(const void* p) {
    uint32_t a;
    asm("{ .reg .u64 t; cvta.to.shared.u64 t, %1; cvt.u32.u64 %0, t; }" : "=r"(a) : "l"(p));
    return a;
}
__device__ __forceinline__ void cp_async16(uint32_t saddr, const void* gaddr) {
    asm volatile("cp.async.ca.shared.global [%0], [%1], 16;" :: "r"(saddr), "l"(gaddr));
}
__device__ __forceinline__ void cp_commit() {
    asm volatile("cp.async.commit_group;");
}
template<int N>
__device__ __forceinline__ void cp_wait() {
    asm volatile("cp.async.wait_group %0;" :: "n"(N));
}
__device__ __forceinline__ void ldmx4(uint32_t* r, uint32_t addr) {
    asm volatile("ldmatrix.sync.aligned.m8n8.x4.shared.b16 {%0,%1,%2,%3}, [%4];"
                 : "=r"(r[0]), "=r"(r[1]), "=r"(r[2]), "=r"(r[3]) : "r"(addr));
}
__device__ __forceinline__ void ldmx4t(uint32_t* r, uint32_t addr) {
    asm volatile("ldmatrix.sync.aligned.m8n8.x4.trans.shared.b16 {%0,%1,%2,%3}, [%4];"
                 : "=r"(r[0]), "=r"(r[1]), "=r"(r[2]), "=r"(r[3]) : "r"(addr));
}
__device__ __forceinline__ void mma16816(float* c, const uint32_t* a, uint32_t b0, uint32_t b1) {
    asm volatile(
        "mma.sync.aligned.m16n8k16.row.col.f32.bf16.bf16.f32 "
        "{%0,%1,%2,%3}, {%4,%5,%6,%7}, {%8,%9}, {%0,%1,%2,%3};"
        : "+f"(c[0]), "+f"(c[1]), "+f"(c[2]), "+f"(c[3])
        : "r"(a[0]), "r"(a[1]), "r"(a[2]), "r"(a[3]), "r"(b0), "r"(b1));
}
__device__ __forceinline__ float ex2(float x) {
    float r; asm("ex2.approx.f32 %0, %1;" : "=f"(r) : "f"(x)); return r;
}
__device__ __forceinline__ void packsplit(float p0, float p1, uint32_t& hi, uint32_t& lo) {
    __nv_bfloat16 h0 = __float2bfloat16_rn(p0), h1 = __float2bfloat16_rn(p1);
    __nv_bfloat162 hv(h0, h1);
    hi = *reinterpret_cast<uint32_t*>(&hv);
    __nv_bfloat162 lv(__float2bfloat16_rn(p0 - __bfloat162float(h0)),
                      __float2bfloat16_rn(p1 - __bfloat162float(h1)));
    lo = *reinterpret_cast<uint32_t*>(&lv);
}

// ---------------- rmsnorm ----------------
__global__ void rmsnorm_kernel(const float* __restrict__ x, const float* __restrict__ w,
                               float* __restrict__ out) {
    int row = blockIdx.x;
    const float* xp = x + (size_t)row * D;
    float v[8];
    float ss = 0.f;
#pragma unroll
    for (int i = 0; i < 8; i++) { v[i] = xp[threadIdx.x + i*256]; ss += v[i]*v[i]; }
    __shared__ float red[256];
    red[threadIdx.x] = ss; __syncthreads();
    for (int s = 128; s > 0; s >>= 1) {
        if (threadIdx.x < s) red[threadIdx.x] += red[threadIdx.x + s];
        __syncthreads();
    }
    float rms = rsqrtf(red[0] / (float)D + EPSV);
    float* op = out + (size_t)row * D;
#pragma unroll
    for (int i = 0; i < 8; i++) { int d = threadIdx.x + i*256; op[d] = v[i]*rms*w[d]; }
}

// ---------------- split fp32 -> bf16 hi/lo ----------------
__global__ void asplit_kernel(const float* __restrict__ x,
                              __nv_bfloat16* __restrict__ hi, __nv_bfloat16* __restrict__ lo) {
    size_t idx = (size_t)blockIdx.x * 256 + threadIdx.x;   // over elems/4
    float4 v = ((const float4*)x)[idx];
    __nv_bfloat16 h0 = __float2bfloat16_rn(v.x), h1 = __float2bfloat16_rn(v.y);
    __nv_bfloat16 h2 = __float2bfloat16_rn(v.z), h3 = __float2bfloat16_rn(v.w);
    __nv_bfloat162* hp = (__nv_bfloat162*)hi;
    __nv_bfloat162* lp = (__nv_bfloat162*)lo;
    hp[2*idx+0] = __nv_bfloat162(h0, h1);
    hp[2*idx+1] = __nv_bfloat162(h2, h3);
    lp[2*idx+0] = __nv_bfloat162(__float2bfloat16_rn(v.x - __bfloat162float(h0)),
                                 __float2bfloat16_rn(v.y - __bfloat162float(h1)));
    lp[2*idx+1] = __nv_bfloat162(__float2bfloat16_rn(v.z - __bfloat162float(h2)),
                                 __float2bfloat16_rn(v.w - __bfloat162float(h3)));
}

// ---------------- transpose + split weights: W[K,N] -> WT[N,K] hi/lo bf16 ----------------
__global__ void wsplit_kernel(const float* __restrict__ W,
                              __nv_bfloat16* __restrict__ th, __nv_bfloat16* __restrict__ tl) {
    __shared__ float t[32][33];
    int n0 = blockIdx.x * 32, k0 = blockIdx.y * 32;
    int tx = threadIdx.x, ty = threadIdx.y;   // 32 x 8
#pragma unroll
    for (int i = 0; i < 4; i++)
        t[ty + 8*i][tx] = W[(size_t)(k0 + ty + 8*i) * D + n0 + tx];
    __syncthreads();
#pragma unroll
    for (int i = 0; i < 4; i++) {
        float v = t[tx][ty + 8*i];
        size_t o = (size_t)(n0 + ty + 8*i) * D + k0 + tx;
        __nv_bfloat16 hv = __float2bfloat16_rn(v);
        th[o] = hv;
        tl[o] = __float2bfloat16_rn(v - __bfloat162float(hv));
    }
}

// ---------------- mma.sync GEMM: C[M,N] = A[M,K] @ B^T (B given [N,K]) ----------------
#define GM 128
#define GN 128
#define GK 32
#define TSTR 40
#define TILE_B2 (128*TSTR*2)
#define STG_B2 (4*TILE_B2)
#define MMA_SMEM (2*STG_B2)

__global__ __launch_bounds__(256, 2)
void mma_gemm_kernel(const __nv_bfloat16* __restrict__ Ah, const __nv_bfloat16* __restrict__ Al,
                     const __nv_bfloat16* __restrict__ Bh, const __nv_bfloat16* __restrict__ Bl,
                     const float* __restrict__ Res, float* __restrict__ C,
                     int Mdim, int Ndim, int Kdim) {
    extern __shared__ char smem[];
    uint32_t sb = smem_u32(smem);
    int tid = threadIdx.x, lane = tid & 31, warp = tid >> 5;
    int wm = warp & 3, wn = warp >> 2;
    int m0 = blockIdx.y * GM, n0 = blockIdx.x * GN;

    int lrow[2], lcol[2];
    uint32_t sdst[2];
#pragma unroll
    for (int p = 0; p < 2; p++) {
        int idx = tid + p*256;
        lrow[p] = idx >> 2;
        lcol[p] = (idx & 3) * 8;
        sdst[p] = (uint32_t)(lrow[p]*TSTR + lcol[p]) * 2;
    }

    const int nkt = Kdim / GK;

    auto issue = [&](int kt, int stage) {
        uint32_t s0 = sb + stage * STG_B2;
        const __nv_bfloat16* srcs[4] = {
            Ah + (size_t)m0 * Kdim, Al + (size_t)m0 * Kdim,
            Bh + (size_t)n0 * Kdim, Bl + (size_t)n0 * Kdim };
#pragma unroll
        for (int tl = 0; tl < 4; tl++) {
#pragma unroll
            for (int p = 0; p < 2; p++) {
                const __nv_bfloat16* g = srcs[tl] + (size_t)lrow[p] * Kdim + kt*GK + lcol[p];
                cp_async16(s0 + tl*TILE_B2 + sdst[p], g);
            }
        }
        cp_commit();
    };

    float acc[2][8][4];
#pragma unroll
    for (int mi = 0; mi < 2; mi++)
#pragma unroll
        for (int nj = 0; nj < 8; nj++)
#pragma unroll
            for (int c = 0; c < 4; c++) acc[mi][nj][c] = 0.f;

    int lr = lane & 15, lc8 = (lane >> 4) << 3;

    issue(0, 0);

    for (int kt = 0; kt < nkt; kt++) {
        int stage = kt & 1;
        if (kt + 1 < nkt) { issue(kt + 1, stage ^ 1); cp_wait<1>(); }
        else              { cp_wait<0>(); }
        __syncthreads();

        uint32_t s0 = sb + stage * STG_B2;
        uint32_t sAh = s0, sAl = s0 + TILE_B2, sBh = s0 + 2*TILE_B2, sBl = s0 + 3*TILE_B2;

#pragma unroll
        for (int ks = 0; ks < 2; ks++) {
            int kc = ks*16 + lc8;
            uint32_t ah[2][4], al[2][4], bh[4][4], bl[4][4];
#pragma unroll
            for (int mi = 0; mi < 2; mi++)
                ldmx4(ah[mi], sAh + (uint32_t)((wm*32 + mi*16 + lr)*TSTR + kc) * 2);
#pragma unroll
            for (int njp = 0; njp < 4; njp++)
                ldmx4(bh[njp], sBh + (uint32_t)((wn*64 + njp*16 + lr)*TSTR + kc) * 2);
#pragma unroll
            for (int mi = 0; mi < 2; mi++)
#pragma unroll
                for (int njp = 0; njp < 4; njp++) {
                    mma16816(acc[mi][2*njp+0], ah[mi], bh[njp][0], bh[njp][2]);
                    mma16816(acc[mi][2*njp+1], ah[mi], bh[njp][1], bh[njp][3]);
                }
#pragma unroll
            for (int mi = 0; mi < 2; mi++)
                ldmx4(al[mi], sAl + (uint32_t)((wm*32 + mi*16 + lr)*TSTR + kc) * 2);
#pragma unroll
            for (int mi = 0; mi < 2; mi++)
#pragma unroll
                for (int njp = 0; njp < 4; njp++) {
                    mma16816(acc[mi][2*njp+0], al[mi], bh[njp][0], bh[njp][2]);
                    mma16816(acc[mi][2*njp+1], al[mi], bh[njp][1], bh[njp][3]);
                }
#pragma unroll
            for (int njp = 0; njp < 4; njp++)
                ldmx4(bl[njp], sBl + (uint32_t)((wn*64 + njp*16 + lr)*TSTR + kc) * 2);
#pragma unroll
            for (int mi = 0; mi < 2; mi++)
#pragma unroll
                for (int njp = 0; njp < 4; njp++) {
                    mma16816(acc[mi][2*njp+0], ah[mi], bl[njp][0], bl[njp][2]);
                    mma16816(acc[mi][2*njp+1], ah[mi], bl[njp][1], bl[njp][3]);
                }
        }
        __syncthreads();
    }

    int g = lane >> 2, tg = lane & 3;
#pragma unroll
    for (int mi = 0; mi < 2; mi++) {
        size_t row0 = (size_t)(m0 + wm*32 + mi*16 + g);
#pragma unroll
        for (int nj = 0; nj < 8; nj++) {
            size_t col = (size_t)(n0 + wn*64 + nj*8 + tg*2);
            float2 v0 = make_float2(acc[mi][nj][0], acc[mi][nj][1]);
            float2 v1 = make_float2(acc[mi][nj][2], acc[mi][nj][3]);
            if (Res) {
                float2 r0 = *(const float2*)(Res + row0*Ndim + col);
                float2 r1 = *(const float2*)(Res + (row0+8)*Ndim + col);
                v0.x += r0.x; v0.y += r0.y; v1.x += r1.x; v1.y += r1.y;
            }
            *(float2*)(C + row0*Ndim + col) = v0;
            *(float2*)(C + (row0+8)*Ndim + col) = v1;
        }
    }
}

// ---------------- RoPE (in-place on q and k) ----------------
__global__ void rope_kernel(float* __restrict__ q, float* __restrict__ k,
                            const float* __restrict__ fc) {
    int idx = blockIdx.x * 256 + threadIdx.x;
    int i = idx & 63;
    int t = (idx >> 10) & (T - 1);
    float2 cs = *(const float2*)(fc + (size_t)t*HD + 2*i);
    float2 qv = ((const float2*)q)[idx];
    float2 kv = ((const float2*)k)[idx];
    ((float2*)q)[idx] = make_float2(qv.x*cs.x - qv.y*cs.y, qv.x*cs.y + qv.y*cs.x);
    ((float2*)k)[idx] = make_float2(kv.x*cs.x - kv.y*cs.y, kv.x*cs.y + kv.y*cs.x);
}

// ---------------- flash attention (mma.sync bf16, 3-term split) ----------------
#define AQ 128
#define AKV 64
#define ASTRB 272                       // smem row stride bytes (136 bf16)
#define ATILE_B (AKV*ASTRB)             // 17408
#define ASTG_B (4*ATILE_B)              // 69632
#define FATTN_SMEM (2*ASTG_B)           // 139264
#define SCL2 0.12751743867f             // (1/sqrt(128)) * log2(e)

__global__ __launch_bounds__(256)
void fattn_kernel(const __nv_bfloat16* __restrict__ Qh, const __nv_bfloat16* __restrict__ Ql,
                  const __nv_bfloat16* __restrict__ Kh, const __nv_bfloat16* __restrict__ Kl,
                  const __nv_bfloat16* __restrict__ Vh, const __nv_bfloat16* __restrict__ Vl,
                  float* __restrict__ Og, const int* __restrict__ causal_flag) {
    extern __shared__ char smem[];
    uint32_t sb = smem_u32(smem);
    int tid = threadIdx.x, lane = tid & 31, warp = tid >> 5;
    int g = lane >> 2, tg = lane & 3;
    int q0 = blockIdx.x * AQ, h = blockIdx.y, b = blockIdx.z;
    bool causal = (*causal_flag) != 0;
    int wrow = q0 + warp * 16;

    uint32_t s0 = sb, s1 = sb + ASTG_B;

    // offset of row t within [B,T,H,HD]: ((b*T+t)*H + h)*HD
    const size_t bbase = ((size_t)b * T) << 11;
    const size_t hbase = (size_t)h * HD;

    // ---- async-load Q (hi|lo) into s0, and kv tile 0 into s1 ----
#pragma unroll
    for (int half = 0; half < 2; half++) {
        const __nv_bfloat16* src = half ? Ql : Qh;
#pragma unroll
        for (int j = 0; j < 8; j++) {
            int c = tid + j*256;
            int r = c >> 4, col = c & 15;
            cp_async16(s0 + half*(AQ*ASTRB) + r*ASTRB + col*16,
                       src + bbase + ((size_t)(q0 + r) << 11) + hbase + col*8);
        }
    }
    cp_commit();

    auto issue_kv = [&](int kvt, uint32_t stg) {
        int k0 = kvt * AKV;
        const __nv_bfloat16* ptrs[4] = {Kh, Kl, Vh, Vl};
#pragma unroll
        for (int tl = 0; tl < 4; tl++) {
#pragma unroll
            for (int j = 0; j < 4; j++) {
                int c = tid + j*256;
                int r = c >> 4, col = c & 15;
                cp_async16(stg + tl*ATILE_B + r*ASTRB + col*16,
                           ptrs[tl] + bbase + ((size_t)(k0 + r) << 11) + hbase + col*8);
            }
        }
        cp_commit();
    };

    int ntile = causal ? (q0 + AQ)/AKV : T/AKV;
    issue_kv(0, s1);

    cp_wait<1>();          // Q ready (kv0 may still be in flight)
    __syncthreads();

    int lr = lane & 15, c8 = (lane >> 4) << 3;
    uint32_t qfh[8][4], qfl[8][4];
#pragma unroll
    for (int ks = 0; ks < 8; ks++) {
        uint32_t a = s0 + (warp*16 + lr)*ASTRB + (ks*16 + c8)*2;
        ldmx4(qfh[ks], a);
        ldmx4(qfl[ks], a + AQ*ASTRB);
    }
    __syncthreads();       // s0 free

    float oa[16][4];
#pragma unroll
    for (int i = 0; i < 16; i++) { oa[i][0]=0.f; oa[i][1]=0.f; oa[i][2]=0.f; oa[i][3]=0.f; }
    float m0 = -1e30f, m1 = -1e30f, l0 = 0.f, l1 = 0.f;

    for (int kvt = 0; kvt < ntile; kvt++) {
        uint32_t cur = (kvt & 1) ? s0 : s1;
        uint32_t nxt = (kvt & 1) ? s1 : s0;
        if (kvt + 1 < ntile) { issue_kv(kvt + 1, nxt); cp_wait<1>(); }
        else                 { cp_wait<0>(); }
        __syncthreads();
        int k0 = kvt * AKV;

        if (!causal || k0 <= wrow + 15) {
            uint32_t KHs = cur, KLs = cur + ATILE_B, VHs = cur + 2*ATILE_B, VLs = cur + 3*ATILE_B;
            // ---- S = Q K^T (3-term) ----
            float sa[8][4];
#pragma unroll
            for (int nj = 0; nj < 8; nj++) { sa[nj][0]=0.f; sa[nj][1]=0.f; sa[nj][2]=0.f; sa[nj][3]=0.f; }
#pragma unroll
            for (int ks = 0; ks < 8; ks++) {
                uint32_t bh[4][4], bl[4][4];
#pragma unroll
                for (int n4 = 0; n4 < 4; n4++)
                    ldmx4(bh[n4], KHs + (n4*16 + lr)*ASTRB + (ks*16 + c8)*2);
#pragma unroll
                for (int n4 = 0; n4 < 4; n4++) {
                    mma16816(sa[2*n4+0], qfh[ks], bh[n4][0], bh[n4][2]);
                    mma16816(sa[2*n4+1], qfh[ks], bh[n4][1], bh[n4][3]);
                }
#pragma unroll
                for (int n4 = 0; n4 < 4; n4++)
                    ldmx4(bl[n4], KLs + (n4*16 + lr)*ASTRB + (ks*16 + c8)*2);
#pragma unroll
                for (int n4 = 0; n4 < 4; n4++) {
                    mma16816(sa[2*n4+0], qfh[ks], bl[n4][0], bl[n4][2]);
                    mma16816(sa[2*n4+1], qfh[ks], bl[n4][1], bl[n4][3]);
                    mma16816(sa[2*n4+0], qfl[ks], bh[n4][0], bh[n4][2]);
                    mma16816(sa[2*n4+1], qfl[ks], bh[n4][1], bh[n4][3]);
                }
            }
            // ---- causal mask ----
            if (causal && k0 + 63 > wrow) {
#pragma unroll
                for (int nj = 0; nj < 8; nj++) {
                    int col = k0 + nj*8 + 2*tg;
                    if (col     > wrow + g)     sa[nj][0] = -1e30f;
                    if (col + 1 > wrow + g)     sa[nj][1] = -1e30f;
                    if (col     > wrow + g + 8) sa[nj][2] = -1e30f;
                    if (col + 1 > wrow + g + 8) sa[nj][3] = -1e30f;
                }
            }
            // ---- online softmax ----
            float mt0 = -1e30f, mt1 = -1e30f;
#pragma unroll
            for (int nj = 0; nj < 8; nj++) {
                mt0 = fmaxf(mt0, fmaxf(sa[nj][0], sa[nj][1]));
                mt1 = fmaxf(mt1, fmaxf(sa[nj][2], sa[nj][3]));
            }
            mt0 = fmaxf(mt0, __shfl_xor_sync(0xffffffffu, mt0, 1));
            mt0 = fmaxf(mt0, __shfl_xor_sync(0xffffffffu, mt0, 2));
            mt1 = fmaxf(mt1, __shfl_xor_sync(0xffffffffu, mt1, 1));
            mt1 = fmaxf(mt1, __shfl_xor_sync(0xffffffffu, mt1, 2));
            float mn0 = fmaxf(m0, mt0), mn1 = fmaxf(m1, mt1);
            float al0 = ex2((m0 - mn0)*SCL2), al1 = ex2((m1 - mn1)*SCL2);
            float nb0 = mn0 * SCL2, nb1 = mn1 * SCL2;
            float ls0 = 0.f, ls1 = 0.f;
#pragma unroll
            for (int nj = 0; nj < 8; nj++) {
                float p0 = ex2(fmaf(sa[nj][0], SCL2, -nb0));
                float p1 = ex2(fmaf(sa[nj][1], SCL2, -nb0));
                float p2 = ex2(fmaf(sa[nj][2], SCL2, -nb1));
                float p3 = ex2(fmaf(sa[nj][3], SCL2, -nb1));
                sa[nj][0]=p0; sa[nj][1]=p1; sa[nj][2]=p2; sa[nj][3]=p3;
                ls0 += p0 + p1; ls1 += p2 + p3;
            }
            ls0 += __shfl_xor_sync(0xffffffffu, ls0, 1);
            ls0 += __shfl_xor_sync(0xffffffffu, ls0, 2);
            ls1 += __shfl_xor_sync(0xffffffffu, ls1, 1);
            ls1 += __shfl_xor_sync(0xffffffffu, ls1, 2);
            l0 = l0*al0 + ls0; l1 = l1*al1 + ls1;
            m0 = mn0; m1 = mn1;
#pragma unroll
            for (int i2 = 0; i2 < 16; i2++) {
                oa[i2][0]*=al0; oa[i2][1]*=al0; oa[i2][2]*=al1; oa[i2][3]*=al1;
            }
            // ---- P fragments (S-acc layout -> A-frag layout, hi/lo split) ----
            uint32_t pfh[4][4], pfl[4][4];
#pragma unroll
            for (int kt = 0; kt < 4; kt++) {
                packsplit(sa[2*kt][0],   sa[2*kt][1],   pfh[kt][0], pfl[kt][0]);
                packsplit(sa[2*kt][2],   sa[2*kt][3],   pfh[kt][1], pfl[kt][1]);
                packsplit(sa[2*kt+1][0], sa[2*kt+1][1], pfh[kt][2], pfl[kt][2]);
                packsplit(sa[2*kt+1][2], sa[2*kt+1][3], pfh[kt][3], pfl[kt][3]);
            }
            // ---- O += P V (3-term), V via ldmatrix.trans ----
            int mlane = lane >> 3;
            int kvr = (mlane & 1)*8 + (lane & 7);
            int hdc = (mlane >> 1)*8;
#pragma unroll
            for (int kt = 0; kt < 4; kt++) {
                uint32_t rbase = (uint32_t)((kt*16 + kvr)*ASTRB + hdc*2);
#pragma unroll
                for (int hp = 0; hp < 8; hp++) {
                    uint32_t vfh[4], vfl[4];
                    ldmx4t(vfh, VHs + rbase + hp*32);
                    ldmx4t(vfl, VLs + rbase + hp*32);
                    mma16816(oa[2*hp+0], pfh[kt], vfh[0], vfh[1]);
                    mma16816(oa[2*hp+1], pfh[kt], vfh[2], vfh[3]);
                    mma16816(oa[2*hp+0], pfh[kt], vfl[0], vfl[1]);
                    mma16816(oa[2*hp+1], pfh[kt], vfl[2], vfl[3]);
                    mma16816(oa[2*hp+0], pfl[kt], vfh[0], vfh[1]);
                    mma16816(oa[2*hp+1], pfl[kt], vfh[2], vfh[3]);
                }
            }
        }
        __syncthreads();
    }

    float inv0 = 1.f / l0, inv1 = 1.f / l1;
    float* o0 = Og + bbase + ((size_t)(wrow + g) << 11) + hbase;
    float* o1 = Og + bbase + ((size_t)(wrow + g + 8) << 11) + hbase;
#pragma unroll
    for (int hp = 0; hp < 16; hp++) {
        int hd = hp*8 + 2*tg;
        *(float2*)(o0 + hd) = make_float2(oa[hp][0]*inv0, oa[hp][1]*inv0);
        *(float2*)(o1 + hd) = make_float2(oa[hp][2]*inv1, oa[hp][3]*inv1);
    }
}

// ---------------- router logits: hn @ slots_w (D x E) ----------------
__global__ void logits_kernel(const float* __restrict__ hn, const float* __restrict__ sw,
                              float* __restrict__ out) {
    int row = blockIdx.x;
    const float* hp = hn + (size_t)row * D;
    float acc[E];
#pragma unroll
    for (int e = 0; e < E; e++) acc[e] = 0.f;
#pragma unroll
    for (int i = 0; i < 8; i++) {
        int d = threadIdx.x + i*256;
        float hv = hp[d];
        const float* swp = sw + (size_t)d * E;
#pragma unroll
        for (int e = 0; e < E; e++) acc[e] += hv * swp[e];
    }
#pragma unroll
    for (int e = 0; e < E; e++)
        for (int o = 16; o > 0; o >>= 1) acc[e] += __shfl_xor_sync(0xffffffffu, acc[e], o);
    __shared__ float red[8][E];
    int warp = threadIdx.x >> 5, lane = threadIdx.x & 31;
    if (lane == 0)
#pragma unroll
        for (int e = 0; e < E; e++) red[warp][e] = acc[e];
    __syncthreads();
    if (threadIdx.x < E) {
        float s = 0.f;
#pragma unroll
        for (int w = 0; w < 8; w++) s += red[w][threadIdx.x];
        out[(size_t)row*E + threadIdx.x] = s;
    }
}

// ---------------- dispatch softmax (over T, per (b,e)) ----------------
__global__ void dispatch_softmax_kernel(const float* __restrict__ lg, float* __restrict__ out) {
    int b = blockIdx.x >> 3, e = blockIdx.x & 7;
    const float* lp = lg + (size_t)b*T*E + e;
    float v[8];
    float m = -1e30f;
#pragma unroll
    for (int i = 0; i < 8; i++) {
        v[i] = lp[(size_t)(threadIdx.x + i*256)*E];
        m = fmaxf(m, v[i]);
    }
    __shared__ float red[256];
    red[threadIdx.x] = m; __syncthreads();
    for (int s = 128; s > 0; s >>= 1) {
        if (threadIdx.x < s) red[threadIdx.x] = fmaxf(red[threadIdx.x], red[threadIdx.x + s]);
        __syncthreads();
    }
    m = red[0]; __syncthreads();
    float ssum = 0.f;
#pragma unroll
    for (int i = 0; i < 8; i++) { v[i] = __expf(v[i] - m); ssum += v[i]; }
    red[threadIdx.x] = ssum; __syncthreads();
    for (int s = 128; s > 0; s >>= 1) {
        if (threadIdx.x < s) red[threadIdx.x] += red[threadIdx.x + s];
        __syncthreads();
    }
    float inv = 1.f / red[0];
    float* op = out + (size_t)b*T*E + e;
#pragma unroll
    for (int i = 0; i < 8; i++) op[(size_t)(threadIdx.x + i*256)*E] = v[i]*inv;
}

// ---------------- combine softmax (over E, per (b,t)) ----------------
__global__ void combine_softmax_kernel(const float* __restrict__ lg, float* __restrict__ out) {
    int row = blockIdx.x*256 + threadIdx.x;
    const float* lp = lg + (size_t)row * E;
    float m = -1e30f;
#pragma unroll
    for (int e = 0; e < E; e++) m = fmaxf(m, lp[e]);
    float ve[E]; float s = 0.f;
#pragma unroll
    for (int e = 0; e < E; e++) { ve[e] = __expf(lp[e] - m); s += ve[e]; }
    float inv = 1.f / s;
    float* op = out + (size_t)row * E;
#pragma unroll
    for (int e = 0; e < E; e++) op[e] = ve[e]*inv;
}

// ---------------- slots = dispatch^T @ hn (per b) ----------------
__global__ void slots_kernel(const float* __restrict__ disp, const float* __restrict__ hn,
                             float* __restrict__ slots) {
    int d = blockIdx.x*256 + threadIdx.x;
    int e = blockIdx.y, b = blockIdx.z;
    __shared__ float sd[256];
    float acc = 0.f;
    for (int t0 = 0; t0 < T; t0 += 256) {
        __syncthreads();
        sd[threadIdx.x] = disp[((size_t)b*T + t0 + threadIdx.x)*E + e];
        __syncthreads();
        const float* hp = hn + ((size_t)b*T + t0)*D + d;
#pragma unroll 8
        for (int tt = 0; tt < 256; tt++) acc += sd[tt] * hp[(size_t)tt*D];
    }
    slots[((size_t)b*E + e)*D + d] = acc;
}

// ---------------- expert up-proj: silu(slots@w1) * (slots@w3) ----------------
__global__ void gact_kernel(const float* __restrict__ slots, const float* __restrict__ w1,
                            const float* __restrict__ w3, float* __restrict__ gact) {
    int hcol = blockIdx.x*256 + threadIdx.x;
    int e = blockIdx.y;
    __shared__ float s0[D], s1[D];
    for (int i = threadIdx.x; i < D; i += 256) {
        s0[i] = slots[((size_t)0*E + e)*D + i];
        s1[i] = slots[((size_t)1*E + e)*D + i];
    }
    __syncthreads();
    float a10 = 0.f, a11 = 0.f, a30 = 0.f, a31 = 0.f;
    const float* w1p = w1 + (size_t)e*D*FH + hcol;
    const float* w3p = w3 + (size_t)e*D*FH + hcol;
#pragma unroll 4
    for (int dd = 0; dd < D; dd++) {
        float w1v = w1p[(size_t)dd*FH];
        float w3v = w3p[(size_t)dd*FH];
        a10 += s0[dd]*w1v; a11 += s1[dd]*w1v;
        a30 += s0[dd]*w3v; a31 += s1[dd]*w3v;
    }
    float g0 = a10 / (1.f + __expf(-a10)) * a30;
    float g1 = a11 / (1.f + __expf(-a11)) * a31;
    gact[((size_t)0*E + e)*FH + hcol] = g0;
    gact[((size_t)1*E + e)*FH + hcol] = g1;
}

// ---------------- expert down-proj, split-K partials ----------------
__global__ void w2_kernel(const float* __restrict__ gact, const float* __restrict__ w2,
                          float* __restrict__ ypart) {
    const int CH = FH / KS;
    int d = blockIdx.x*256 + threadIdx.x;
    int e = blockIdx.y;
    int kc = blockIdx.z;
    __shared__ float gg0[FH / KS], gg1[FH / KS];
    for (int i = threadIdx.x; i < CH; i += 256) {
        gg0[i] = gact[((size_t)0*E + e)*FH + kc*CH + i];
        gg1[i] = gact[((size_t)1*E + e)*FH + kc*CH + i];
    }
    __syncthreads();
    float a0 = 0.f, a1 = 0.f;
    const float* w2p = w2 + ((size_t)e*FH + (size_t)kc*CH)*D + d;
#pragma unroll 4
    for (int hh = 0; hh < CH; hh++) {
        float wv = w2p[(size_t)hh*D];
        a0 += gg0[hh]*wv; a1 += gg1[hh]*wv;
    }
    ypart[((size_t)kc*B*E + 0*E + e)*D + d] = a0;
    ypart[((size_t)kc*B*E + 1*E + e)*D + d] = a1;
}

__global__ void yreduce_kernel(const float* __restrict__ ypart, float* __restrict__ y) {
    int i = blockIdx.x*256 + threadIdx.x;
    float s = 0.f;
#pragma unroll
    for (int kc = 0; kc < KS; kc++) s += ypart[(size_t)kc*B*E*D + i];
    y[i] = s;
}

// ---------------- final: out = h + combine @ y ----------------
__global__ void final_kernel(const float* __restrict__ h, const float* __restrict__ comb,
                             const float* __restrict__ y, float* __restrict__ out) {
    int row = blockIdx.x;
    int b = row / T;
    float c[E];
    const float* cp = comb + (size_t)row*E;
#pragma unroll
    for (int e = 0; e < E; e++) c[e] = cp[e];
#pragma unroll
    for (int i = 0; i < 8; i++) {
        int d = threadIdx.x + i*256;
        float acc = h[(size_t)row*D + d];
#pragma unroll
        for (int e = 0; e < E; e++) acc += c[e] * y[((size_t)b*E + e)*D + d];
        out[(size_t)row*D + d] = acc;
    }
}

// ---------------- launch ----------------
extern "C" void kernel_launch(void* const* d_in, const int* in_sizes, int n_in,
                              void* d_out, int out_size) {
    const float* x   = (const float*)d_in[0];
    const float* fc  = (const float*)d_in[3];
    const float* wq  = (const float*)d_in[4];
    const float* wk  = (const float*)d_in[5];
    const float* wv  = (const float*)d_in[6];
    const float* wo  = (const float*)d_in[7];
    const float* sw  = (const float*)d_in[8];
    const float* w1  = (const float*)d_in[9];
    const float* w3  = (const float*)d_in[10];
    const float* w2  = (const float*)d_in[11];
    const float* anw = (const float*)d_in[12];
    const float* fnw = (const float*)d_in[13];
    const int* causal = (const int*)d_in[14];
    float* out = (float*)d_out;

    float *xn, *q, *k, *v, *attn, *h, *hn, *logits, *disp, *comb, *slots, *gact, *ypart, *y;
    __nv_bfloat16 *ah, *al, *kh, *kl, *vh, *vl, *wth, *wtl;
    cudaGetSymbolAddress((void**)&xn,    g_xn);
    cudaGetSymbolAddress((void**)&q,     g_q);
    cudaGetSymbolAddress((void**)&k,     g_k);
    cudaGetSymbolAddress((void**)&v,     g_v);
    cudaGetSymbolAddress((void**)&attn,  g_attn);
    cudaGetSymbolAddress((void**)&h,     g_h);
    cudaGetSymbolAddress((void**)&hn,    g_hn);
    cudaGetSymbolAddress((void**)&logits,g_logits);
    cudaGetSymbolAddress((void**)&disp,  g_disp);
    cudaGetSymbolAddress((void**)&comb,  g_comb);
    cudaGetSymbolAddress((void**)&slots, g_slots);
    cudaGetSymbolAddress((void**)&gact,  g_gact);
    cudaGetSymbolAddress((void**)&ypart, g_ypart);
    cudaGetSymbolAddress((void**)&y,     g_y);
    cudaGetSymbolAddress((void**)&ah,    g_ah);
    cudaGetSymbolAddress((void**)&al,    g_al);
    cudaGetSymbolAddress((void**)&kh,    g_kh);
    cudaGetSymbolAddress((void**)&kl,    g_kl);
    cudaGetSymbolAddress((void**)&vh,    g_vh);
    cudaGetSymbolAddress((void**)&vl,    g_vl);
    cudaGetSymbolAddress((void**)&wth,   g_wth);
    cudaGetSymbolAddress((void**)&wtl,   g_wtl);

    cudaFuncSetAttribute(mma_gemm_kernel, cudaFuncAttributeMaxDynamicSharedMemorySize, MMA_SMEM);
    cudaFuncSetAttribute(fattn_kernel, cudaFuncAttributeMaxDynamicSharedMemorySize, FATTN_SMEM);

    const size_t NK = (size_t)D * D;
    const int NSPL = (int)(((size_t)MT * D / 4) / 256);

    rmsnorm_kernel<<<MT, 256>>>(x, anw, xn);
    asplit_kernel<<<NSPL, 256>>>(xn, ah, al);

    dim3 wgrid(D/32, D/32);
    wsplit_kernel<<<wgrid, dim3(32,8)>>>(wq, wth + 0*NK, wtl + 0*NK);
    wsplit_kernel<<<wgrid, dim3(32,8)>>>(wk, wth + 1*NK, wtl + 1*NK);
    wsplit_kernel<<<wgrid, dim3(32,8)>>>(wv, wth + 2*NK, wtl + 2*NK);
    wsplit_kernel<<<wgrid, dim3(32,8)>>>(wo, wth + 3*NK, wtl + 3*NK);

    dim3 gg(D/GN, MT/GM);
    mma_gemm_kernel<<<gg, 256, MMA_SMEM>>>(ah, al, wth + 0*NK, wtl + 0*NK, nullptr, q, MT, D, D);
    mma_gemm_kernel<<<gg, 256, MMA_SMEM>>>(ah, al, wth + 1*NK, wtl + 1*NK, nullptr, k, MT, D, D);
    mma_gemm_kernel<<<gg, 256, MMA_SMEM>>>(ah, al, wth + 2*NK, wtl + 2*NK, nullptr, v, MT, D, D);

    rope_kernel<<<(B*T*H*(HD/2))/256, 256>>>(q, k, fc);

    // split q/k/v to bf16 hi/lo (q reuses ah/al — xn split no longer needed)
    asplit_kernel<<<NSPL, 256>>>(q, ah, al);
    asplit_kernel<<<NSPL, 256>>>(k, kh, kl);
    asplit_kernel<<<NSPL, 256>>>(v, vh, vl);

    fattn_kernel<<<dim3(T/AQ, H, B), 256, FATTN_SMEM>>>(ah, al, kh, kl, vh, vl, attn, causal);

    asplit_kernel<<<NSPL, 256>>>(attn, ah, al);
    mma_gemm_kernel<<<gg, 256, MMA_SMEM>>>(ah, al, wth + 3*NK, wtl + 3*NK, xn, h, MT, D, D);

    rmsnorm_kernel<<<MT, 256>>>(h, fnw, hn);

    logits_kernel<<<MT, 256>>>(hn, sw, logits);
    dispatch_softmax_kernel<<<B*E, 256>>>(logits, disp);
    combine_softmax_kernel<<<MT/256, 256>>>(logits, comb);

    slots_kernel<<<dim3(D/256, E, B), 256>>>(disp, hn, slots);
    gact_kernel<<<dim3(FH/256, E), 256>>>(slots, w1, w3, gact);
    w2_kernel<<<dim3(D/256, E, KS), 256>>>(gact, w2, ypart);
    yreduce_kernel<<<(B*E*D)/256, 256>>>(ypart, y);

    final_kernel<<<MT, 256>>>(h, comb, y, out);
}